// round 1
// baseline (speedup 1.0000x reference)
#include <cuda_runtime.h>
#include <cuda_bf16.h>
#include <cstdint>

// Problem constants
#define BDIM 4
#define NDIM 2048
#define CDIM 1024
#define HDIM 16
#define DHEAD 64
#define MROWS (BDIM * NDIM)          // 8192
#define QKVCOLS (3 * CDIM)           // 3072
#define NEGVAL (-10000000.0f)

// Scratch (device globals: allocation-free, graph-capturable)
__device__ float g_qkv[(size_t)MROWS * QKVCOLS];   // 8192 x 3072
__device__ float g_ctx[(size_t)MROWS * CDIM];      // 8192 x 1024

// ---------------------------------------------------------------------------
// SGEMM: C[M,N] = A[M,K] @ B[K,N] (+ bias). 128x128 tile, BK=16, 256 thr, 8x8 micro.
// All dims assumed multiples of tile sizes (true here).
// ---------------------------------------------------------------------------
template <bool HAS_BIAS>
__global__ __launch_bounds__(256) void sgemm128(
    const float* __restrict__ A, const float* __restrict__ Bm,
    const float* __restrict__ bias, float* __restrict__ Cm,
    int Mdim, int Ndim, int Kdim)
{
    __shared__ float As[16][132];   // transposed A tile, padded
    __shared__ float Bs[16][128];

    const int tid = threadIdx.x;
    const int tx = tid & 15;        // 0..15 -> output cols tx*8..+7
    const int ty = tid >> 4;        // 0..15 -> output rows ty*8..+7
    const int n0 = blockIdx.x * 128;
    const int m0 = blockIdx.y * 128;

    float acc[8][8];
#pragma unroll
    for (int i = 0; i < 8; ++i)
#pragma unroll
        for (int j = 0; j < 8; ++j) acc[i][j] = 0.0f;

    const float* Aptr = A + (size_t)m0 * Kdim;

    for (int k0 = 0; k0 < Kdim; k0 += 16) {
        __syncthreads();
        // Load A tile (128x16) transposed into As
#pragma unroll
        for (int r = 0; r < 2; ++r) {
            int arow = (tid >> 2) + r * 64;
            int ac4 = (tid & 3) * 4;
            float4 v = *(const float4*)(Aptr + (size_t)arow * Kdim + k0 + ac4);
            As[ac4 + 0][arow] = v.x;
            As[ac4 + 1][arow] = v.y;
            As[ac4 + 2][arow] = v.z;
            As[ac4 + 3][arow] = v.w;
        }
        // Load B tile (16x128)
#pragma unroll
        for (int r = 0; r < 2; ++r) {
            int brow = (tid >> 5) + r * 8;
            int bc = (tid & 31) * 4;
            *(float4*)&Bs[brow][bc] =
                *(const float4*)(Bm + (size_t)(k0 + brow) * Ndim + n0 + bc);
        }
        __syncthreads();

#pragma unroll
        for (int kk = 0; kk < 16; ++kk) {
            float a[8], bb[8];
            *(float4*)&a[0]  = *(float4*)&As[kk][ty * 8];
            *(float4*)&a[4]  = *(float4*)&As[kk][ty * 8 + 4];
            *(float4*)&bb[0] = *(float4*)&Bs[kk][tx * 8];
            *(float4*)&bb[4] = *(float4*)&Bs[kk][tx * 8 + 4];
#pragma unroll
            for (int i = 0; i < 8; ++i)
#pragma unroll
                for (int j = 0; j < 8; ++j)
                    acc[i][j] = fmaf(a[i], bb[j], acc[i][j]);
        }
    }

    // Epilogue
#pragma unroll
    for (int i = 0; i < 8; ++i) {
        int row = m0 + ty * 8 + i;
        float* cp = Cm + (size_t)row * Ndim + n0 + tx * 8;
        if (HAS_BIAS) {
            const float* bp = bias + n0 + tx * 8;
#pragma unroll
            for (int j = 0; j < 8; ++j) acc[i][j] += bp[j];
        }
        *(float4*)&cp[0] = make_float4(acc[i][0], acc[i][1], acc[i][2], acc[i][3]);
        *(float4*)&cp[4] = make_float4(acc[i][4], acc[i][5], acc[i][6], acc[i][7]);
    }
}

// ---------------------------------------------------------------------------
// Flash attention. One CTA per (b,h, 64-row q tile). 128 threads.
// smem: Qt[64][68] (d-major), KPt[64][68] (K tile d-major, reused for P^T), Vs[64][64].
// Thread map: tx = tid&7 -> 8 cols (k-cols for S / d-cols for O), ty = tid>>3 -> 4 rows.
// ---------------------------------------------------------------------------
#define AT_LD 68
#define AT_SMEM_FLOATS (64 * AT_LD * 2 + 64 * 64)
#define AT_SMEM_BYTES (AT_SMEM_FLOATS * 4)

__global__ __launch_bounds__(128) void attn_kernel(
    const float* __restrict__ qkv, const int* __restrict__ attn_mask,
    const int* __restrict__ pad_mask, float* __restrict__ ctx)
{
    extern __shared__ float sm[];
    float* Qt  = sm;                      // 64 * AT_LD
    float* KPt = sm + 64 * AT_LD;         // 64 * AT_LD (K^T tile, then P^T)
    float* Vs  = sm + 2 * 64 * AT_LD;     // 64 * 64

    const int tid = threadIdx.x;
    const int tx = tid & 7;               // col group
    const int ty = tid >> 3;              // row group (0..15)
    const int n0 = blockIdx.x * 64;
    const int bh = blockIdx.y;
    const int b = bh >> 4;
    const int h = bh & 15;

    const float* qbase = qkv + (size_t)(b * NDIM + n0) * QKVCOLS + h * DHEAD;
    const float* kbase = qkv + (size_t)(b * NDIM) * QKVCOLS + CDIM + h * DHEAD;
    const float* vbase = qkv + (size_t)(b * NDIM) * QKVCOLS + 2 * CDIM + h * DHEAD;

    // Load Q tile transposed: Qt[d][row]
#pragma unroll
    for (int it = 0; it < 8; ++it) {
        int idx = it * 128 + tid;         // float4 index 0..1023
        int r = idx >> 4;                 // row 0..63
        int c4 = (idx & 15) * 4;          // d offset
        float4 v = *(const float4*)(qbase + (size_t)r * QKVCOLS + c4);
        Qt[(c4 + 0) * AT_LD + r] = v.x;
        Qt[(c4 + 1) * AT_LD + r] = v.y;
        Qt[(c4 + 2) * AT_LD + r] = v.z;
        Qt[(c4 + 3) * AT_LD + r] = v.w;
    }

    float m_i[4], l_i[4], acc[4][8];
#pragma unroll
    for (int i = 0; i < 4; ++i) {
        m_i[i] = -1e30f;
        l_i[i] = 0.0f;
#pragma unroll
        for (int j = 0; j < 8; ++j) acc[i][j] = 0.0f;
    }
    const float scale = 0.125f;           // 64^-0.5

    for (int kt = 0; kt < NDIM / 64; ++kt) {
        const int k0 = kt * 64;
        __syncthreads();   // protects KPt/Vs reuse from prev iter; makes Qt visible (kt==0)

        // Load K tile transposed KPt[d][kcol], V tile direct Vs[kcol][d]
#pragma unroll
        for (int it = 0; it < 8; ++it) {
            int idx = it * 128 + tid;
            int r = idx >> 4;
            int c4 = (idx & 15) * 4;
            float4 kv = *(const float4*)(kbase + (size_t)(k0 + r) * QKVCOLS + c4);
            KPt[(c4 + 0) * AT_LD + r] = kv.x;
            KPt[(c4 + 1) * AT_LD + r] = kv.y;
            KPt[(c4 + 2) * AT_LD + r] = kv.z;
            KPt[(c4 + 3) * AT_LD + r] = kv.w;
            float4 vv = *(const float4*)(vbase + (size_t)(k0 + r) * QKVCOLS + c4);
            *(float4*)&Vs[r * 64 + c4] = vv;
        }
        __syncthreads();

        // S = Q @ K^T  (4x8 micro-tile per thread)
        float s[4][8];
#pragma unroll
        for (int i = 0; i < 4; ++i)
#pragma unroll
            for (int j = 0; j < 8; ++j) s[i][j] = 0.0f;

#pragma unroll
        for (int kk = 0; kk < DHEAD; ++kk) {
            float a[4], bb[8];
            *(float4*)&a[0]  = *(float4*)&Qt[kk * AT_LD + ty * 4];
            *(float4*)&bb[0] = *(float4*)&KPt[kk * AT_LD + tx * 8];
            *(float4*)&bb[4] = *(float4*)&KPt[kk * AT_LD + tx * 8 + 4];
#pragma unroll
            for (int i = 0; i < 4; ++i)
#pragma unroll
                for (int j = 0; j < 8; ++j)
                    s[i][j] = fmaf(a[i], bb[j], s[i][j]);
        }

        // Masks: attn_mask[nq, nk] <= 0 -> NEG; padding_mask[b, nk] > 0 -> NEG
        int4 p0 = *(const int4*)(pad_mask + b * NDIM + k0 + tx * 8);
        int4 p1 = *(const int4*)(pad_mask + b * NDIM + k0 + tx * 8 + 4);
        int pads[8] = {p0.x, p0.y, p0.z, p0.w, p1.x, p1.y, p1.z, p1.w};
#pragma unroll
        for (int i = 0; i < 4; ++i) {
            const int nq = n0 + ty * 4 + i;
            int4 a0 = *(const int4*)(attn_mask + (size_t)nq * NDIM + k0 + tx * 8);
            int4 a1 = *(const int4*)(attn_mask + (size_t)nq * NDIM + k0 + tx * 8 + 4);
            int ams[8] = {a0.x, a0.y, a0.z, a0.w, a1.x, a1.y, a1.z, a1.w};
#pragma unroll
            for (int j = 0; j < 8; ++j) {
                bool keep = (ams[j] > 0) && (pads[j] <= 0);
                s[i][j] = keep ? s[i][j] * scale : NEGVAL;
            }
        }

        // Online softmax per row (reduce across the 8 tx lanes)
#pragma unroll
        for (int i = 0; i < 4; ++i) {
            float mloc = s[i][0];
#pragma unroll
            for (int j = 1; j < 8; ++j) mloc = fmaxf(mloc, s[i][j]);
#pragma unroll
            for (int off = 1; off < 8; off <<= 1)
                mloc = fmaxf(mloc, __shfl_xor_sync(0xffffffffu, mloc, off));
            const float mnew = fmaxf(m_i[i], mloc);
            const float corr = __expf(m_i[i] - mnew);
            m_i[i] = mnew;
            float lsum = 0.0f;
#pragma unroll
            for (int j = 0; j < 8; ++j) {
                s[i][j] = __expf(s[i][j] - mnew);
                lsum += s[i][j];
            }
#pragma unroll
            for (int off = 1; off < 8; off <<= 1)
                lsum += __shfl_xor_sync(0xffffffffu, lsum, off);
            l_i[i] = l_i[i] * corr + lsum;
#pragma unroll
            for (int j = 0; j < 8; ++j) acc[i][j] *= corr;
        }

        __syncthreads();   // everyone done reading KPt (K^T) before overwrite with P^T

        // Write P^T into KPt: Pt[kcol][qrow]
#pragma unroll
        for (int j = 0; j < 8; ++j) {
            *(float4*)&KPt[(tx * 8 + j) * AT_LD + ty * 4] =
                make_float4(s[0][j], s[1][j], s[2][j], s[3][j]);
        }
        __syncthreads();

        // O += P @ V
#pragma unroll
        for (int kc = 0; kc < 64; ++kc) {
            float a[4], bb[8];
            *(float4*)&a[0]  = *(float4*)&KPt[kc * AT_LD + ty * 4];
            *(float4*)&bb[0] = *(float4*)&Vs[kc * 64 + tx * 8];
            *(float4*)&bb[4] = *(float4*)&Vs[kc * 64 + tx * 8 + 4];
#pragma unroll
            for (int i = 0; i < 4; ++i)
#pragma unroll
                for (int j = 0; j < 8; ++j)
                    acc[i][j] = fmaf(a[i], bb[j], acc[i][j]);
        }
    }

    // Epilogue: normalize and store ctx[b, n, h*64 + d]
#pragma unroll
    for (int i = 0; i < 4; ++i) {
        const float inv = 1.0f / l_i[i];
        const int row = n0 + ty * 4 + i;
        float* cp = ctx + (size_t)(b * NDIM + row) * CDIM + h * DHEAD + tx * 8;
        *(float4*)&cp[0] = make_float4(acc[i][0] * inv, acc[i][1] * inv,
                                       acc[i][2] * inv, acc[i][3] * inv);
        *(float4*)&cp[4] = make_float4(acc[i][4] * inv, acc[i][5] * inv,
                                       acc[i][6] * inv, acc[i][7] * inv);
    }
}

// ---------------------------------------------------------------------------
extern "C" void kernel_launch(void* const* d_in, const int* in_sizes, int n_in,
                              void* d_out, int out_size)
{
    const float* X       = (const float*)d_in[0];
    const int* attn_mask = (const int*)d_in[1];
    const int* pad_mask  = (const int*)d_in[2];
    const float* Wqkv    = (const float*)d_in[3];
    const float* Wproj   = (const float*)d_in[4];
    const float* bias    = (const float*)d_in[5];
    float* out           = (float*)d_out;

    float *qkv = nullptr, *ctx = nullptr;
    cudaGetSymbolAddress((void**)&qkv, g_qkv);
    cudaGetSymbolAddress((void**)&ctx, g_ctx);

    // 1) QKV projection: [8192,1024] @ [1024,3072]
    sgemm128<false><<<dim3(QKVCOLS / 128, MROWS / 128), 256>>>(
        X, Wqkv, nullptr, qkv, MROWS, QKVCOLS, CDIM);

    // 2) Flash attention per (b,h,q-tile)
    cudaFuncSetAttribute(attn_kernel,
                         cudaFuncAttributeMaxDynamicSharedMemorySize, AT_SMEM_BYTES);
    attn_kernel<<<dim3(NDIM / 64, BDIM * HDIM), 128, AT_SMEM_BYTES>>>(
        qkv, attn_mask, pad_mask, ctx);

    // 3) Output projection + bias: [8192,1024] @ [1024,1024]
    sgemm128<true><<<dim3(CDIM / 128, MROWS / 128), 256>>>(
        ctx, Wproj, bias, out, MROWS, CDIM, CDIM);
}

// round 3
// speedup vs baseline: 3.6364x; 3.6364x over previous
#include <cuda_runtime.h>
#include <cuda_bf16.h>
#include <cstdint>

// Problem constants
#define BDIM 4
#define NDIM 2048
#define CDIM 1024
#define HDIM 16
#define DHEAD 64
#define MROWS 8192
#define QKVCOLS 3072
#define KDIM 1024
#define NEGVAL (-10000000.0f)

// Scratch (device globals: allocation-free, graph-capturable)
__device__ float g_qkv[(size_t)MROWS * QKVCOLS];      // 8192 x 3072
__device__ float g_ctx[(size_t)MROWS * CDIM];         // 8192 x 1024 (tf32-rounded)
__device__ float g_Xc[(size_t)MROWS * KDIM];          // tf32-rounded input
__device__ float g_WqkvT[(size_t)QKVCOLS * KDIM];     // [N,K] tf32-rounded
__device__ float g_WprojT[(size_t)CDIM * KDIM];       // [N,K] tf32-rounded
__device__ unsigned long long g_attnP[(size_t)NDIM * (NDIM / 64)];  // bit = attn>0
__device__ unsigned long long g_padP[BDIM * (NDIM / 64)];           // bit = pad<=0

// ---------------------------------------------------------------------------
// Helpers
// ---------------------------------------------------------------------------
__device__ __forceinline__ uint32_t smem_u32(const void* p) {
    uint32_t a;
    asm("{ .reg .u64 t; cvta.to.shared.u64 t, %1; cvt.u32.u64 %0, t; }"
        : "=r"(a) : "l"(p));
    return a;
}

__device__ __forceinline__ uint32_t f2tf(float f) {
    uint32_t o;
    asm("cvt.rna.tf32.f32 %0, %1;" : "=r"(o) : "f"(f));
    return o;
}

__device__ __forceinline__ void ldm4(uint32_t* r, uint32_t addr) {
    asm volatile("ldmatrix.sync.aligned.m8n8.x4.shared.b16 {%0,%1,%2,%3}, [%4];"
                 : "=r"(r[0]), "=r"(r[1]), "=r"(r[2]), "=r"(r[3]) : "r"(addr));
}

__device__ __forceinline__ void mma8(float* d, const uint32_t* a,
                                     uint32_t b0, uint32_t b1) {
    asm volatile(
        "mma.sync.aligned.m16n8k8.row.col.f32.tf32.tf32.f32 "
        "{%0,%1,%2,%3},{%4,%5,%6,%7},{%8,%9},{%0,%1,%2,%3};"
        : "+f"(d[0]), "+f"(d[1]), "+f"(d[2]), "+f"(d[3])
        : "r"(a[0]), "r"(a[1]), "r"(a[2]), "r"(a[3]), "r"(b0), "r"(b1));
}

__device__ __forceinline__ void cpa16(uint32_t s, const void* g) {
    asm volatile("cp.async.cg.shared.global [%0], [%1], 16;" :: "r"(s), "l"(g));
}
#define CP_COMMIT() asm volatile("cp.async.commit_group;" ::: "memory")
#define CP_WAIT1()  asm volatile("cp.async.wait_group 1;" ::: "memory")

// ---------------------------------------------------------------------------
// Mask packing
// ---------------------------------------------------------------------------
__global__ __launch_bounds__(256) void pack_attn(
    const int* __restrict__ attn, unsigned long long* __restrict__ attnP)
{
    int w = blockIdx.x * 8 + (threadIdx.x >> 5);
    int lane = threadIdx.x & 31;
    int nq = w >> 5, kb = w & 31;
    const int* p = attn + (size_t)nq * NDIM + kb * 64;
    unsigned b0 = __ballot_sync(~0u, p[lane] > 0);
    unsigned b1 = __ballot_sync(~0u, p[lane + 32] > 0);
    if (lane == 0) attnP[w] = (unsigned long long)b0 | ((unsigned long long)b1 << 32);
}

__global__ __launch_bounds__(256) void pack_pad(
    const int* __restrict__ pad, unsigned long long* __restrict__ padP)
{
    int w = blockIdx.x * 8 + (threadIdx.x >> 5);
    int lane = threadIdx.x & 31;
    if (w < BDIM * 32) {
        int b = w >> 5, kb = w & 31;
        const int* p = pad + b * NDIM + kb * 64;
        unsigned b0 = __ballot_sync(~0u, p[lane] <= 0);
        unsigned b1 = __ballot_sync(~0u, p[lane + 32] <= 0);
        if (lane == 0) padP[w] = (unsigned long long)b0 | ((unsigned long long)b1 << 32);
    }
}

// ---------------------------------------------------------------------------
// tf32 rounding pass (vectorized)
// ---------------------------------------------------------------------------
__global__ __launch_bounds__(256) void cvt_tf32_vec(
    const float* __restrict__ in, float* __restrict__ out, int n4)
{
    int i = blockIdx.x * 256 + threadIdx.x;
    if (i < n4) {
        float4 v = ((const float4*)in)[i];
        uint4 u = make_uint4(f2tf(v.x), f2tf(v.y), f2tf(v.z), f2tf(v.w));
        ((uint4*)out)[i] = u;
    }
}

// Transpose + tf32 round: out[n][k] = tf32(in[k][n]).
__global__ __launch_bounds__(256) void transpose32(
    const float* __restrict__ in, float* __restrict__ out, int rows, int cols)
{
    __shared__ float t[32][33];
    const int bx = blockIdx.x * 32, by = blockIdx.y * 32;
    const int txl = threadIdx.x, tyl = threadIdx.y;
#pragma unroll
    for (int i = tyl; i < 32; i += 8)
        t[i][txl] = in[(size_t)(by + i) * cols + bx + txl];
    __syncthreads();
#pragma unroll
    for (int i = tyl; i < 32; i += 8)
        out[(size_t)(bx + i) * rows + by + txl] = __uint_as_float(f2tf(t[txl][i]));
}

// ---------------------------------------------------------------------------
// tf32 mma GEMM: C[M,Ncols] = A[M,1024] @ Bt[Ncols,1024]^T (+bias)
// 128x128 tile, BK=32, 256 thr (8 warps 2x4), cp.async double buffer.
// ---------------------------------------------------------------------------
#define GS_A0 0
#define GS_A1 16384
#define GS_B0 32768
#define GS_B1 49152
#define GS_TOTAL 65536

template <bool HAS_BIAS>
__global__ __launch_bounds__(256, 2) void gemm_mma(
    const float* __restrict__ A, const float* __restrict__ Bt,
    const float* __restrict__ bias, float* __restrict__ Cm, int Ncols)
{
    extern __shared__ char smem[];
    const uint32_t sb = smem_u32(smem);
    const int tid = threadIdx.x, lane = tid & 31, wid = tid >> 5;
    const int mw = wid >> 2, nw = wid & 3;
    const int n0 = blockIdx.x * 128, m0 = blockIdx.y * 128;

    const uint32_t sA[2] = {sb + GS_A0, sb + GS_A1};
    const uint32_t sB[2] = {sb + GS_B0, sb + GS_B1};
    const float* Ag = A + (size_t)m0 * KDIM;
    const float* Bg = Bt + (size_t)n0 * KDIM;

    float c[4][4][4];
#pragma unroll
    for (int i = 0; i < 4; ++i)
#pragma unroll
        for (int j = 0; j < 4; ++j)
#pragma unroll
            for (int k = 0; k < 4; ++k) c[i][j][k] = 0.0f;

    auto loadChunk = [&](int ch, int bf) {
        const int kc = ch * 32;
#pragma unroll
        for (int i = 0; i < 4; ++i) {
            int idx = i * 256 + tid;
            int r = idx >> 3;
            int cB = (idx & 7) * 16;
            uint32_t so = (uint32_t)(r * 128 + (cB ^ ((r & 7) << 4)));
            cpa16(sA[bf] + so, Ag + (size_t)r * KDIM + kc + (idx & 7) * 4);
            cpa16(sB[bf] + so, Bg + (size_t)r * KDIM + kc + (idx & 7) * 4);
        }
    };

    loadChunk(0, 0);
    CP_COMMIT();

    const int lrow = ((lane >> 3) & 1) * 8 + (lane & 7);
    const int hib = ((lane >> 4) & 1) * 16;

    for (int ch = 0; ch < 32; ++ch) {
        if (ch < 31) loadChunk(ch + 1, (ch + 1) & 1);
        CP_COMMIT();
        CP_WAIT1();
        __syncthreads();

        const uint32_t aB = sA[ch & 1], bB = sB[ch & 1];
#pragma unroll
        for (int ks = 0; ks < 4; ++ks) {
            const int cb = ks * 32 + hib;
            uint32_t a[4][4];
#pragma unroll
            for (int mf = 0; mf < 4; ++mf) {
                int r = mw * 64 + mf * 16 + lrow;
                ldm4(a[mf], aB + r * 128 + (cb ^ ((r & 7) << 4)));
            }
            uint32_t bfr[2][4];
#pragma unroll
            for (int bf2 = 0; bf2 < 2; ++bf2) {
                int r = nw * 32 + bf2 * 16 + lrow;
                ldm4(bfr[bf2], bB + r * 128 + (cb ^ ((r & 7) << 4)));
            }
#pragma unroll
            for (int mf = 0; mf < 4; ++mf)
#pragma unroll
                for (int nf = 0; nf < 4; ++nf)
                    mma8(c[mf][nf], a[mf], bfr[nf >> 1][nf & 1], bfr[nf >> 1][(nf & 1) + 2]);
        }
        __syncthreads();
    }

    const int g = lane >> 2, tig = lane & 3;
#pragma unroll
    for (int mf = 0; mf < 4; ++mf) {
        int r0 = m0 + mw * 64 + mf * 16 + g;
#pragma unroll
        for (int nf = 0; nf < 4; ++nf) {
            int col = n0 + nw * 32 + nf * 8 + tig * 2;
            float b0 = 0.0f, b1 = 0.0f;
            if (HAS_BIAS) { b0 = bias[col]; b1 = bias[col + 1]; }
            *(float2*)(Cm + (size_t)r0 * Ncols + col) =
                make_float2(c[mf][nf][0] + b0, c[mf][nf][1] + b1);
            *(float2*)(Cm + (size_t)(r0 + 8) * Ncols + col) =
                make_float2(c[mf][nf][2] + b0, c[mf][nf][3] + b1);
        }
    }
}

// ---------------------------------------------------------------------------
// Flash attention with tf32 mma. CTA: 128 q-rows x (b,h). 256 thr, 8 warps.
// Warp: 16 q-rows x 64 keys. K-block = 64 keys.
// smem: Qs[128][64] 32KB | Ks[64][64] 16KB | Vt[64][64] 16KB | Ps[128][64] 32KB
// ---------------------------------------------------------------------------
#define AS_Q 0
#define AS_K 32768
#define AS_V 49152
#define AS_P 65536
#define AS_TOTAL 98304

__global__ __launch_bounds__(256, 2) void attn_mma(
    const float* __restrict__ qkv,
    const unsigned long long* __restrict__ attnP,
    const unsigned long long* __restrict__ padP,
    float* __restrict__ ctx)
{
    extern __shared__ char smem[];
    const uint32_t sb = smem_u32(smem);
    const int tid = threadIdx.x, lane = tid & 31, wid = tid >> 5;
    const int g = lane >> 2, tig = lane & 3;
    const int lrow = ((lane >> 3) & 1) * 8 + (lane & 7);
    const int hib = ((lane >> 4) & 1) * 16;

    const int n0 = blockIdx.x * 128;
    const int bh = blockIdx.y;
    const int b = bh >> 4, h = bh & 15;

    const float* qbase = qkv + (size_t)(b * NDIM + n0) * QKVCOLS + h * DHEAD;
    const float* kbase = qkv + (size_t)b * NDIM * QKVCOLS + CDIM + h * DHEAD;
    const float* vbase = qkv + (size_t)b * NDIM * QKVCOLS + 2 * CDIM + h * DHEAD;

    // Load Q tile (tf32-rounded)
#pragma unroll
    for (int i = 0; i < 8; ++i) {
        int idx = i * 256 + tid;
        int r = idx >> 4;
        int c4 = (idx & 15) * 4;
        float4 v = *(const float4*)(qbase + (size_t)r * QKVCOLS + c4);
        uint4 u = make_uint4(f2tf(v.x), f2tf(v.y), f2tf(v.z), f2tf(v.w));
        *(uint4*)(smem + AS_Q + r * 256 + ((c4 * 4) ^ ((r & 7) << 4))) = u;
    }

    float oc[8][4];
#pragma unroll
    for (int f = 0; f < 8; ++f)
#pragma unroll
        for (int j = 0; j < 4; ++j) oc[f][j] = 0.0f;
    float m0r = -1e30f, m1r = -1e30f, l0 = 0.0f, l1 = 0.0f;

    const int qrow0 = n0 + wid * 16 + g;      // global q row (half 0)
    const float scale = 0.125f;

    for (int kt = 0; kt < NDIM / 64; ++kt) {
        __syncthreads();
        // K tile [key][d]
#pragma unroll
        for (int i = 0; i < 4; ++i) {
            int idx = i * 256 + tid;
            int r = idx >> 4;
            int c4 = (idx & 15) * 4;
            float4 v = *(const float4*)(kbase + (size_t)(kt * 64 + r) * QKVCOLS + c4);
            uint4 u = make_uint4(f2tf(v.x), f2tf(v.y), f2tf(v.z), f2tf(v.w));
            *(uint4*)(smem + AS_K + r * 256 + ((c4 * 4) ^ ((r & 7) << 4))) = u;
        }
        // V tile transposed: Vt[d][key]
#pragma unroll
        for (int i = 0; i < 4; ++i) {
            int idx = i * 256 + tid;
            int key = idx >> 4;
            int d4 = (idx & 15) * 4;
            float4 v = *(const float4*)(vbase + (size_t)(kt * 64 + key) * QKVCOLS + d4);
            uint32_t vals[4] = {f2tf(v.x), f2tf(v.y), f2tf(v.z), f2tf(v.w)};
#pragma unroll
            for (int j = 0; j < 4; ++j) {
                int d = d4 + j;
                *(uint32_t*)(smem + AS_V + d * 256 + ((key * 4) ^ ((d & 7) << 4))) = vals[j];
            }
        }
        __syncthreads();

        // S = Q @ K^T
        float sc[8][4];
#pragma unroll
        for (int f = 0; f < 8; ++f)
#pragma unroll
            for (int j = 0; j < 4; ++j) sc[f][j] = 0.0f;

#pragma unroll
        for (int ks = 0; ks < 8; ++ks) {
            const int cb = ks * 32 + hib;
            uint32_t a[4];
            {
                int r = wid * 16 + lrow;
                ldm4(a, sb + AS_Q + r * 256 + (cb ^ ((r & 7) << 4)));
            }
#pragma unroll
            for (int f = 0; f < 4; ++f) {
                uint32_t bf[4];
                int rk = f * 16 + lrow;
                ldm4(bf, sb + AS_K + rk * 256 + (cb ^ ((rk & 7) << 4)));
                mma8(sc[f * 2 + 0], a, bf[0], bf[2]);
                mma8(sc[f * 2 + 1], a, bf[1], bf[3]);
            }
        }

        // Masks
        const unsigned long long pw = padP[b * 32 + kt];
        const unsigned long long a0w = attnP[(size_t)qrow0 * 32 + kt] & pw;
        const unsigned long long a1w = attnP[(size_t)(qrow0 + 8) * 32 + kt] & pw;
#pragma unroll
        for (int f = 0; f < 8; ++f) {
            int j0 = f * 8 + tig * 2;
            sc[f][0] = ((a0w >> j0) & 1ull)       ? sc[f][0] * scale : NEGVAL;
            sc[f][1] = ((a0w >> (j0 + 1)) & 1ull) ? sc[f][1] * scale : NEGVAL;
            sc[f][2] = ((a1w >> j0) & 1ull)       ? sc[f][2] * scale : NEGVAL;
            sc[f][3] = ((a1w >> (j0 + 1)) & 1ull) ? sc[f][3] * scale : NEGVAL;
        }

        // Online softmax (rows live in 4-lane groups)
        float mb0 = sc[0][0], mb1 = sc[0][2];
#pragma unroll
        for (int f = 0; f < 8; ++f) {
            mb0 = fmaxf(mb0, fmaxf(sc[f][0], sc[f][1]));
            mb1 = fmaxf(mb1, fmaxf(sc[f][2], sc[f][3]));
        }
        mb0 = fmaxf(mb0, __shfl_xor_sync(~0u, mb0, 1));
        mb0 = fmaxf(mb0, __shfl_xor_sync(~0u, mb0, 2));
        mb1 = fmaxf(mb1, __shfl_xor_sync(~0u, mb1, 1));
        mb1 = fmaxf(mb1, __shfl_xor_sync(~0u, mb1, 2));

        const float mn0 = fmaxf(m0r, mb0), mn1 = fmaxf(m1r, mb1);
        const float corr0 = __expf(m0r - mn0), corr1 = __expf(m1r - mn1);
        m0r = mn0; m1r = mn1;

        float s0 = 0.0f, s1 = 0.0f;
#pragma unroll
        for (int f = 0; f < 8; ++f) {
            float p0 = __uint_as_float(f2tf(__expf(sc[f][0] - mn0)));
            float p1 = __uint_as_float(f2tf(__expf(sc[f][1] - mn0)));
            float p2 = __uint_as_float(f2tf(__expf(sc[f][2] - mn1)));
            float p3 = __uint_as_float(f2tf(__expf(sc[f][3] - mn1)));
            sc[f][0] = p0; sc[f][1] = p1; sc[f][2] = p2; sc[f][3] = p3;
            s0 += p0 + p1;
            s1 += p2 + p3;
        }
        s0 += __shfl_xor_sync(~0u, s0, 1);
        s0 += __shfl_xor_sync(~0u, s0, 2);
        s1 += __shfl_xor_sync(~0u, s1, 1);
        s1 += __shfl_xor_sync(~0u, s1, 2);
        l0 = l0 * corr0 + s0;
        l1 = l1 * corr1 + s1;
#pragma unroll
        for (int f = 0; f < 8; ++f) {
            oc[f][0] *= corr0; oc[f][1] *= corr0;
            oc[f][2] *= corr1; oc[f][3] *= corr1;
        }

        // P -> smem (warp-private rows)
        const int rl0 = wid * 16 + g, rl1 = rl0 + 8;
#pragma unroll
        for (int f = 0; f < 8; ++f) {
            int cbyte = (f * 8 + tig * 2) * 4;
            *(float2*)(smem + AS_P + rl0 * 256 + (cbyte ^ ((rl0 & 7) << 4))) =
                make_float2(sc[f][0], sc[f][1]);
            *(float2*)(smem + AS_P + rl1 * 256 + (cbyte ^ ((rl1 & 7) << 4))) =
                make_float2(sc[f][2], sc[f][3]);
        }
        __syncwarp();

        // O += P @ V
#pragma unroll
        for (int ks = 0; ks < 8; ++ks) {
            const int cb = ks * 32 + hib;
            uint32_t a[4];
            {
                int r = wid * 16 + lrow;
                ldm4(a, sb + AS_P + r * 256 + (cb ^ ((r & 7) << 4)));
            }
#pragma unroll
            for (int f = 0; f < 4; ++f) {
                uint32_t bf[4];
                int rd = f * 16 + lrow;
                ldm4(bf, sb + AS_V + rd * 256 + (cb ^ ((rd & 7) << 4)));
                mma8(oc[f * 2 + 0], a, bf[0], bf[2]);
                mma8(oc[f * 2 + 1], a, bf[1], bf[3]);
            }
        }
    }

    // Epilogue: normalize, tf32-round (feeds proj GEMM), store
    const float inv0 = 1.0f / l0, inv1 = 1.0f / l1;
#pragma unroll
    for (int f = 0; f < 8; ++f) {
        int col = h * DHEAD + f * 8 + tig * 2;
        float* p0 = ctx + (size_t)(b * NDIM + qrow0) * CDIM + col;
        float* p1 = ctx + (size_t)(b * NDIM + qrow0 + 8) * CDIM + col;
        *(float2*)p0 = make_float2(__uint_as_float(f2tf(oc[f][0] * inv0)),
                                   __uint_as_float(f2tf(oc[f][1] * inv0)));
        *(float2*)p1 = make_float2(__uint_as_float(f2tf(oc[f][2] * inv1)),
                                   __uint_as_float(f2tf(oc[f][3] * inv1)));
    }
}

// ---------------------------------------------------------------------------
extern "C" void kernel_launch(void* const* d_in, const int* in_sizes, int n_in,
                              void* d_out, int out_size)
{
    const float* X       = (const float*)d_in[0];
    const int* attn_mask = (const int*)d_in[1];
    const int* pad_mask  = (const int*)d_in[2];
    const float* Wqkv    = (const float*)d_in[3];
    const float* Wproj   = (const float*)d_in[4];
    const float* bias    = (const float*)d_in[5];
    float* out           = (float*)d_out;

    float *qkv, *ctx, *xc, *wqkvT, *wprojT;
    unsigned long long *attnP, *padP;
    cudaGetSymbolAddress((void**)&qkv, g_qkv);
    cudaGetSymbolAddress((void**)&ctx, g_ctx);
    cudaGetSymbolAddress((void**)&xc, g_Xc);
    cudaGetSymbolAddress((void**)&wqkvT, g_WqkvT);
    cudaGetSymbolAddress((void**)&wprojT, g_WprojT);
    cudaGetSymbolAddress((void**)&attnP, g_attnP);
    cudaGetSymbolAddress((void**)&padP, g_padP);

    // Mask packing + operand rounding
    pack_attn<<<(NDIM * 32) / 8, 256>>>(attn_mask, attnP);
    pack_pad<<<16, 256>>>(pad_mask, padP);
    cvt_tf32_vec<<<(MROWS * KDIM / 4) / 256, 256>>>(X, xc, MROWS * KDIM / 4);
    transpose32<<<dim3(QKVCOLS / 32, KDIM / 32), dim3(32, 8)>>>(Wqkv, wqkvT, KDIM, QKVCOLS);
    transpose32<<<dim3(CDIM / 32, KDIM / 32), dim3(32, 8)>>>(Wproj, wprojT, KDIM, CDIM);

    // QKV projection
    cudaFuncSetAttribute(gemm_mma<false>,
                         cudaFuncAttributeMaxDynamicSharedMemorySize, GS_TOTAL);
    cudaFuncSetAttribute(gemm_mma<true>,
                         cudaFuncAttributeMaxDynamicSharedMemorySize, GS_TOTAL);
    gemm_mma<false><<<dim3(QKVCOLS / 128, MROWS / 128), 256, GS_TOTAL>>>(
        xc, wqkvT, nullptr, qkv, QKVCOLS);

    // Attention
    cudaFuncSetAttribute(attn_mma,
                         cudaFuncAttributeMaxDynamicSharedMemorySize, AS_TOTAL);
    attn_mma<<<dim3(NDIM / 128, BDIM * HDIM), 256, AS_TOTAL>>>(
        qkv, attnP, padP, ctx);

    // Output projection + bias
    gemm_mma<true><<<dim3(CDIM / 128, MROWS / 128), 256, GS_TOTAL>>>(
        ctx, wprojT, bias, out, CDIM);
}

// round 4
// speedup vs baseline: 4.0162x; 1.1045x over previous
#include <cuda_runtime.h>
#include <cuda_bf16.h>
#include <cstdint>

// Problem constants
#define BDIM 4
#define NDIM 2048
#define CDIM 1024
#define HDIM 16
#define DHEAD 64
#define MROWS 8192
#define QKVCOLS 3072
#define KDIM 1024
#define NEGVAL (-10000000.0f)

// Scratch (device globals: allocation-free, graph-capturable)
__device__ float g_qkv[(size_t)MROWS * QKVCOLS];      // 8192 x 3072 (tf32-rounded)
__device__ float g_ctx[(size_t)MROWS * CDIM];         // 8192 x 1024 (tf32-rounded)
__device__ float g_Xc[(size_t)MROWS * KDIM];          // tf32-rounded input
__device__ float g_WqkvT[(size_t)QKVCOLS * KDIM];     // [N,K] tf32-rounded
__device__ float g_WprojT[(size_t)CDIM * KDIM];       // [N,K] tf32-rounded
__device__ float g_vT[(size_t)BDIM * HDIM * DHEAD * NDIM]; // V^T per head [bh][d][key]
__device__ unsigned long long g_attnP[(size_t)NDIM * (NDIM / 64)];
__device__ unsigned long long g_padP[BDIM * (NDIM / 64)];

// ---------------------------------------------------------------------------
// Helpers
// ---------------------------------------------------------------------------
__device__ __forceinline__ uint32_t smem_u32(const void* p) {
    uint32_t a;
    asm("{ .reg .u64 t; cvta.to.shared.u64 t, %1; cvt.u32.u64 %0, t; }"
        : "=r"(a) : "l"(p));
    return a;
}

__device__ __forceinline__ uint32_t f2tf(float f) {
    uint32_t o;
    asm("cvt.rna.tf32.f32 %0, %1;" : "=r"(o) : "f"(f));
    return o;
}

__device__ __forceinline__ void ldm4(uint32_t* r, uint32_t addr) {
    asm volatile("ldmatrix.sync.aligned.m8n8.x4.shared.b16 {%0,%1,%2,%3}, [%4];"
                 : "=r"(r[0]), "=r"(r[1]), "=r"(r[2]), "=r"(r[3]) : "r"(addr));
}

__device__ __forceinline__ void mma8(float* d, const uint32_t* a,
                                     uint32_t b0, uint32_t b1) {
    asm volatile(
        "mma.sync.aligned.m16n8k8.row.col.f32.tf32.tf32.f32 "
        "{%0,%1,%2,%3},{%4,%5,%6,%7},{%8,%9},{%0,%1,%2,%3};"
        : "+f"(d[0]), "+f"(d[1]), "+f"(d[2]), "+f"(d[3])
        : "r"(a[0]), "r"(a[1]), "r"(a[2]), "r"(a[3]), "r"(b0), "r"(b1));
}

__device__ __forceinline__ void cpa16(uint32_t s, const void* g) {
    asm volatile("cp.async.cg.shared.global [%0], [%1], 16;" :: "r"(s), "l"(g));
}
#define CP_COMMIT() asm volatile("cp.async.commit_group;" ::: "memory")
#define CP_WAIT1()  asm volatile("cp.async.wait_group 1;" ::: "memory")

// ---------------------------------------------------------------------------
// Mask packing
// ---------------------------------------------------------------------------
__global__ __launch_bounds__(256) void pack_attn(
    const int* __restrict__ attn, unsigned long long* __restrict__ attnP)
{
    int w = blockIdx.x * 8 + (threadIdx.x >> 5);
    int lane = threadIdx.x & 31;
    int nq = w >> 5, kb = w & 31;
    const int* p = attn + (size_t)nq * NDIM + kb * 64;
    unsigned b0 = __ballot_sync(~0u, p[lane] > 0);
    unsigned b1 = __ballot_sync(~0u, p[lane + 32] > 0);
    if (lane == 0) attnP[w] = (unsigned long long)b0 | ((unsigned long long)b1 << 32);
}

__global__ __launch_bounds__(256) void pack_pad(
    const int* __restrict__ pad, unsigned long long* __restrict__ padP)
{
    int w = blockIdx.x * 8 + (threadIdx.x >> 5);
    int lane = threadIdx.x & 31;
    if (w < BDIM * 32) {
        int b = w >> 5, kb = w & 31;
        const int* p = pad + b * NDIM + kb * 64;
        unsigned b0 = __ballot_sync(~0u, p[lane] <= 0);
        unsigned b1 = __ballot_sync(~0u, p[lane + 32] <= 0);
        if (lane == 0) padP[w] = (unsigned long long)b0 | ((unsigned long long)b1 << 32);
    }
}

// ---------------------------------------------------------------------------
// tf32 rounding pass / weight transpose / V transpose
// ---------------------------------------------------------------------------
__global__ __launch_bounds__(256) void cvt_tf32_vec(
    const float* __restrict__ in, float* __restrict__ out, int n4)
{
    int i = blockIdx.x * 256 + threadIdx.x;
    if (i < n4) {
        float4 v = ((const float4*)in)[i];
        ((uint4*)out)[i] = make_uint4(f2tf(v.x), f2tf(v.y), f2tf(v.z), f2tf(v.w));
    }
}

__global__ __launch_bounds__(256) void transpose32(
    const float* __restrict__ in, float* __restrict__ out, int rows, int cols)
{
    __shared__ float t[32][33];
    const int bx = blockIdx.x * 32, by = blockIdx.y * 32;
    const int txl = threadIdx.x, tyl = threadIdx.y;
#pragma unroll
    for (int i = tyl; i < 32; i += 8)
        t[i][txl] = in[(size_t)(by + i) * cols + bx + txl];
    __syncthreads();
#pragma unroll
    for (int i = tyl; i < 32; i += 8)
        out[(size_t)(bx + i) * rows + by + txl] = __uint_as_float(f2tf(t[txl][i]));
}

// V^T: vT[bh][d][key] = qkv[b, key, 2048 + h*64 + d]   (input already rounded)
__global__ __launch_bounds__(256) void vtrans(
    const float* __restrict__ qkv, float* __restrict__ vT)
{
    __shared__ float t[32][33];
    const int key0 = blockIdx.x * 32, d0 = blockIdx.y * 32;
    const int bh = blockIdx.z;
    const int b = bh >> 4, h = bh & 15;
    const int txl = threadIdx.x, tyl = threadIdx.y;
    const float* src = qkv + (size_t)b * NDIM * QKVCOLS + 2 * CDIM + h * DHEAD;
#pragma unroll
    for (int i = tyl; i < 32; i += 8)
        t[i][txl] = src[(size_t)(key0 + i) * QKVCOLS + d0 + txl];
    __syncthreads();
    float* dst = vT + (size_t)bh * DHEAD * NDIM;
#pragma unroll
    for (int i = tyl; i < 32; i += 8)
        dst[(size_t)(d0 + i) * NDIM + key0 + txl] = t[txl][i];
}

// ---------------------------------------------------------------------------
// tf32 mma GEMM: 128x128 tile, BK=32, 3-stage cp.async pipeline, 1 sync/chunk.
// ---------------------------------------------------------------------------
#define GS_STAGE 32768
#define GS_TOTAL (3 * GS_STAGE)   // 96 KB

template <bool HAS_BIAS, bool ROUND_OUT>
__global__ __launch_bounds__(256, 2) void gemm_mma(
    const float* __restrict__ A, const float* __restrict__ Bt,
    const float* __restrict__ bias, float* __restrict__ Cm, int Ncols)
{
    extern __shared__ char smem[];
    const uint32_t sb = smem_u32(smem);
    const int tid = threadIdx.x, lane = tid & 31, wid = tid >> 5;
    const int mw = wid >> 2, nw = wid & 3;
    const int n0 = blockIdx.x * 128, m0 = blockIdx.y * 128;

    const float* Ag = A + (size_t)m0 * KDIM;
    const float* Bg = Bt + (size_t)n0 * KDIM;

    float c[4][4][4];
#pragma unroll
    for (int i = 0; i < 4; ++i)
#pragma unroll
        for (int j = 0; j < 4; ++j)
#pragma unroll
            for (int k = 0; k < 4; ++k) c[i][j][k] = 0.0f;

    auto loadChunk = [&](int ch) {
        const int s = ch % 3;
        const uint32_t aB = sb + s * GS_STAGE, bB = aB + 16384;
        const int kc = ch * 32;
#pragma unroll
        for (int i = 0; i < 4; ++i) {
            int idx = i * 256 + tid;
            int r = idx >> 3;
            int cB = (idx & 7) * 16;
            uint32_t so = (uint32_t)(r * 128 + (cB ^ ((r & 7) << 4)));
            cpa16(aB + so, Ag + (size_t)r * KDIM + kc + (idx & 7) * 4);
            cpa16(bB + so, Bg + (size_t)r * KDIM + kc + (idx & 7) * 4);
        }
    };

    loadChunk(0); CP_COMMIT();
    loadChunk(1); CP_COMMIT();

    const int lrow = ((lane >> 3) & 1) * 8 + (lane & 7);
    const int hib = ((lane >> 4) & 1) * 16;

    for (int ch = 0; ch < 32; ++ch) {
        CP_WAIT1();
        __syncthreads();
        if (ch < 30) loadChunk(ch + 2);
        CP_COMMIT();

        const int s = ch % 3;
        const uint32_t aB = sb + s * GS_STAGE, bB = aB + 16384;
#pragma unroll
        for (int ks = 0; ks < 4; ++ks) {
            const int cb = ks * 32 + hib;
            uint32_t a[4][4];
#pragma unroll
            for (int mf = 0; mf < 4; ++mf) {
                int r = mw * 64 + mf * 16 + lrow;
                ldm4(a[mf], aB + r * 128 + (cb ^ ((r & 7) << 4)));
            }
            uint32_t bfr[2][4];
#pragma unroll
            for (int bf2 = 0; bf2 < 2; ++bf2) {
                int r = nw * 32 + bf2 * 16 + lrow;
                ldm4(bfr[bf2], bB + r * 128 + (cb ^ ((r & 7) << 4)));
            }
#pragma unroll
            for (int mf = 0; mf < 4; ++mf)
#pragma unroll
                for (int nf = 0; nf < 4; ++nf)
                    mma8(c[mf][nf], a[mf], bfr[nf >> 1][nf & 1], bfr[nf >> 1][(nf & 1) + 2]);
        }
    }

    const int g = lane >> 2, tig = lane & 3;
#pragma unroll
    for (int mf = 0; mf < 4; ++mf) {
        int r0 = m0 + mw * 64 + mf * 16 + g;
#pragma unroll
        for (int nf = 0; nf < 4; ++nf) {
            int col = n0 + nw * 32 + nf * 8 + tig * 2;
            float b0 = 0.0f, b1 = 0.0f;
            if (HAS_BIAS) { b0 = bias[col]; b1 = bias[col + 1]; }
            float v00 = c[mf][nf][0] + b0, v01 = c[mf][nf][1] + b1;
            float v10 = c[mf][nf][2] + b0, v11 = c[mf][nf][3] + b1;
            if (ROUND_OUT) {
                v00 = __uint_as_float(f2tf(v00)); v01 = __uint_as_float(f2tf(v01));
                v10 = __uint_as_float(f2tf(v10)); v11 = __uint_as_float(f2tf(v11));
            }
            *(float2*)(Cm + (size_t)r0 * Ncols + col) = make_float2(v00, v01);
            *(float2*)(Cm + (size_t)(r0 + 8) * Ncols + col) = make_float2(v10, v11);
        }
    }
}

// ---------------------------------------------------------------------------
// Flash attention, tf32 mma, cp.async double-buffered K/V^T, Q frags hoisted.
// CTA: 128 q-rows x (b,h), 256 thr, 8 warps, warp = 16 q x 64 keys.
// smem: QP 32KB (Q then P) | K0,K1,V0,V1 16KB each = 96KB total.
// ---------------------------------------------------------------------------
#define AS_QP 0
#define AS_K0 32768
#define AS_K1 49152
#define AS_V0 65536
#define AS_V1 81920
#define AS_TOTAL 98304

__global__ __launch_bounds__(256, 2) void attn_mma(
    const float* __restrict__ qkv, const float* __restrict__ vT,
    const unsigned long long* __restrict__ attnP,
    const unsigned long long* __restrict__ padP,
    float* __restrict__ ctx)
{
    extern __shared__ char smem[];
    const uint32_t sb = smem_u32(smem);
    const int tid = threadIdx.x, lane = tid & 31, wid = tid >> 5;
    const int g = lane >> 2, tig = lane & 3;
    const int lrow = ((lane >> 3) & 1) * 8 + (lane & 7);
    const int hib = ((lane >> 4) & 1) * 16;

    const int n0 = blockIdx.x * 128;
    const int bh = blockIdx.y;
    const int b = bh >> 4, h = bh & 15;

    const float* qbase = qkv + (size_t)(b * NDIM + n0) * QKVCOLS + h * DHEAD;
    const float* kbase = qkv + (size_t)b * NDIM * QKVCOLS + CDIM + h * DHEAD;
    const float* vtb   = vT + (size_t)bh * DHEAD * NDIM;

    const uint32_t sK[2] = {sb + AS_K0, sb + AS_K1};
    const uint32_t sV[2] = {sb + AS_V0, sb + AS_V1};

    // cp.async K/V^T tile kt into buffer bf
    auto loadKV = [&](int kt, int bf) {
#pragma unroll
        for (int i = 0; i < 4; ++i) {
            int idx = i * 256 + tid;
            int r = idx >> 4;
            int c16 = idx & 15;
            uint32_t so = (uint32_t)(r * 256 + ((c16 * 16) ^ ((r & 7) << 4)));
            cpa16(sK[bf] + so, kbase + (size_t)(kt * 64 + r) * QKVCOLS + c16 * 4);
            cpa16(sV[bf] + so, vtb + (size_t)r * NDIM + kt * 64 + c16 * 4);
        }
    };

    // Group 0: Q tile + K0/V0
#pragma unroll
    for (int i = 0; i < 8; ++i) {
        int idx = i * 256 + tid;
        int r = idx >> 4;
        int c16 = idx & 15;
        uint32_t so = (uint32_t)(r * 256 + ((c16 * 16) ^ ((r & 7) << 4)));
        cpa16(sb + AS_QP + so, qbase + (size_t)r * QKVCOLS + c16 * 4);
    }
    loadKV(0, 0);
    CP_COMMIT();

    float oc[8][4];
#pragma unroll
    for (int f = 0; f < 8; ++f)
#pragma unroll
        for (int j = 0; j < 4; ++j) oc[f][j] = 0.0f;
    float m0r = -1e30f, m1r = -1e30f, l0 = 0.0f, l1 = 0.0f;
    uint32_t qf[8][4];

    const int qrow0 = n0 + wid * 16 + g;
    const float scale = 0.125f;

    for (int kt = 0; kt < NDIM / 64; ++kt) {
        __syncthreads();                      // prev compute done before buffer overwrite
        if (kt < 31) loadKV(kt + 1, (kt + 1) & 1);
        CP_COMMIT();
        CP_WAIT1();                           // chunk kt (and Q at kt=0) arrived
        __syncthreads();

        if (kt == 0) {
            // Hoist Q fragments (warp-private rows), then QP becomes P space
#pragma unroll
            for (int ks = 0; ks < 8; ++ks) {
                int r = wid * 16 + lrow;
                ldm4(qf[ks], sb + AS_QP + r * 256 + ((ks * 32 + hib) ^ ((r & 7) << 4)));
            }
            __syncwarp();
        }

        const uint32_t kB = sK[kt & 1], vB = sV[kt & 1];

        // S = Q @ K^T
        float sc[8][4];
#pragma unroll
        for (int f = 0; f < 8; ++f)
#pragma unroll
            for (int j = 0; j < 4; ++j) sc[f][j] = 0.0f;

#pragma unroll
        for (int ks = 0; ks < 8; ++ks) {
            const int cb = ks * 32 + hib;
#pragma unroll
            for (int f = 0; f < 4; ++f) {
                uint32_t bf[4];
                int rk = f * 16 + lrow;
                ldm4(bf, kB + rk * 256 + (cb ^ ((rk & 7) << 4)));
                mma8(sc[f * 2 + 0], qf[ks], bf[0], bf[2]);
                mma8(sc[f * 2 + 1], qf[ks], bf[1], bf[3]);
            }
        }

        // Masks
        const unsigned long long pw = padP[b * 32 + kt];
        const unsigned long long a0w = attnP[(size_t)qrow0 * 32 + kt] & pw;
        const unsigned long long a1w = attnP[(size_t)(qrow0 + 8) * 32 + kt] & pw;
#pragma unroll
        for (int f = 0; f < 8; ++f) {
            int j0 = f * 8 + tig * 2;
            sc[f][0] = ((a0w >> j0) & 1ull)       ? sc[f][0] * scale : NEGVAL;
            sc[f][1] = ((a0w >> (j0 + 1)) & 1ull) ? sc[f][1] * scale : NEGVAL;
            sc[f][2] = ((a1w >> j0) & 1ull)       ? sc[f][2] * scale : NEGVAL;
            sc[f][3] = ((a1w >> (j0 + 1)) & 1ull) ? sc[f][3] * scale : NEGVAL;
        }

        // Online softmax (row = 4-lane group)
        float mb0 = sc[0][0], mb1 = sc[0][2];
#pragma unroll
        for (int f = 0; f < 8; ++f) {
            mb0 = fmaxf(mb0, fmaxf(sc[f][0], sc[f][1]));
            mb1 = fmaxf(mb1, fmaxf(sc[f][2], sc[f][3]));
        }
        mb0 = fmaxf(mb0, __shfl_xor_sync(~0u, mb0, 1));
        mb0 = fmaxf(mb0, __shfl_xor_sync(~0u, mb0, 2));
        mb1 = fmaxf(mb1, __shfl_xor_sync(~0u, mb1, 1));
        mb1 = fmaxf(mb1, __shfl_xor_sync(~0u, mb1, 2));

        const float mn0 = fmaxf(m0r, mb0), mn1 = fmaxf(m1r, mb1);
        const float corr0 = __expf(m0r - mn0), corr1 = __expf(m1r - mn1);
        m0r = mn0; m1r = mn1;

        float s0 = 0.0f, s1 = 0.0f;
#pragma unroll
        for (int f = 0; f < 8; ++f) {
            float p0 = __uint_as_float(f2tf(__expf(sc[f][0] - mn0)));
            float p1 = __uint_as_float(f2tf(__expf(sc[f][1] - mn0)));
            float p2 = __uint_as_float(f2tf(__expf(sc[f][2] - mn1)));
            float p3 = __uint_as_float(f2tf(__expf(sc[f][3] - mn1)));
            sc[f][0] = p0; sc[f][1] = p1; sc[f][2] = p2; sc[f][3] = p3;
            s0 += p0 + p1;
            s1 += p2 + p3;
        }
        s0 += __shfl_xor_sync(~0u, s0, 1);
        s0 += __shfl_xor_sync(~0u, s0, 2);
        s1 += __shfl_xor_sync(~0u, s1, 1);
        s1 += __shfl_xor_sync(~0u, s1, 2);
        l0 = l0 * corr0 + s0;
        l1 = l1 * corr1 + s1;
#pragma unroll
        for (int f = 0; f < 8; ++f) {
            oc[f][0] *= corr0; oc[f][1] *= corr0;
            oc[f][2] *= corr1; oc[f][3] *= corr1;
        }

        // P -> smem (warp-private rows in QP region)
        const int rl0 = wid * 16 + g, rl1 = rl0 + 8;
#pragma unroll
        for (int f = 0; f < 8; ++f) {
            int cbyte = (f * 8 + tig * 2) * 4;
            *(float2*)(smem + AS_QP + rl0 * 256 + (cbyte ^ ((rl0 & 7) << 4))) =
                make_float2(sc[f][0], sc[f][1]);
            *(float2*)(smem + AS_QP + rl1 * 256 + (cbyte ^ ((rl1 & 7) << 4))) =
                make_float2(sc[f][2], sc[f][3]);
        }
        __syncwarp();

        // O += P @ V  (V^T tile: rows = d, cols = keys)
#pragma unroll
        for (int ks = 0; ks < 8; ++ks) {
            const int cb = ks * 32 + hib;
            uint32_t a[4];
            {
                int r = wid * 16 + lrow;
                ldm4(a, sb + AS_QP + r * 256 + (cb ^ ((r & 7) << 4)));
            }
#pragma unroll
            for (int f = 0; f < 4; ++f) {
                uint32_t bf[4];
                int rd = f * 16 + lrow;
                ldm4(bf, vB + rd * 256 + (cb ^ ((rd & 7) << 4)));
                mma8(oc[f * 2 + 0], a, bf[0], bf[2]);
                mma8(oc[f * 2 + 1], a, bf[1], bf[3]);
            }
        }
    }

    // Epilogue: normalize, tf32-round (feeds proj GEMM), store
    const float inv0 = 1.0f / l0, inv1 = 1.0f / l1;
#pragma unroll
    for (int f = 0; f < 8; ++f) {
        int col = h * DHEAD + f * 8 + tig * 2;
        float* p0 = ctx + (size_t)(b * NDIM + qrow0) * CDIM + col;
        float* p1 = ctx + (size_t)(b * NDIM + qrow0 + 8) * CDIM + col;
        *(float2*)p0 = make_float2(__uint_as_float(f2tf(oc[f][0] * inv0)),
                                   __uint_as_float(f2tf(oc[f][1] * inv0)));
        *(float2*)p1 = make_float2(__uint_as_float(f2tf(oc[f][2] * inv1)),
                                   __uint_as_float(f2tf(oc[f][3] * inv1)));
    }
}

// ---------------------------------------------------------------------------
extern "C" void kernel_launch(void* const* d_in, const int* in_sizes, int n_in,
                              void* d_out, int out_size)
{
    const float* X       = (const float*)d_in[0];
    const int* attn_mask = (const int*)d_in[1];
    const int* pad_mask  = (const int*)d_in[2];
    const float* Wqkv    = (const float*)d_in[3];
    const float* Wproj   = (const float*)d_in[4];
    const float* bias    = (const float*)d_in[5];
    float* out           = (float*)d_out;

    float *qkv, *ctx, *xc, *wqkvT, *wprojT, *vT;
    unsigned long long *attnP, *padP;
    cudaGetSymbolAddress((void**)&qkv, g_qkv);
    cudaGetSymbolAddress((void**)&ctx, g_ctx);
    cudaGetSymbolAddress((void**)&xc, g_Xc);
    cudaGetSymbolAddress((void**)&wqkvT, g_WqkvT);
    cudaGetSymbolAddress((void**)&wprojT, g_WprojT);
    cudaGetSymbolAddress((void**)&vT, g_vT);
    cudaGetSymbolAddress((void**)&attnP, g_attnP);
    cudaGetSymbolAddress((void**)&padP, g_padP);

    // Prep: masks + rounded operands
    pack_attn<<<(NDIM * 32) / 8, 256>>>(attn_mask, attnP);
    pack_pad<<<16, 256>>>(pad_mask, padP);
    cvt_tf32_vec<<<(MROWS * KDIM / 4) / 256, 256>>>(X, xc, MROWS * KDIM / 4);
    transpose32<<<dim3(QKVCOLS / 32, KDIM / 32), dim3(32, 8)>>>(Wqkv, wqkvT, KDIM, QKVCOLS);
    transpose32<<<dim3(CDIM / 32, KDIM / 32), dim3(32, 8)>>>(Wproj, wprojT, KDIM, CDIM);

    // QKV projection (outputs tf32-rounded)
    cudaFuncSetAttribute(gemm_mma<false, true>,
                         cudaFuncAttributeMaxDynamicSharedMemorySize, GS_TOTAL);
    cudaFuncSetAttribute(gemm_mma<true, false>,
                         cudaFuncAttributeMaxDynamicSharedMemorySize, GS_TOTAL);
    gemm_mma<false, true><<<dim3(QKVCOLS / 128, MROWS / 128), 256, GS_TOTAL>>>(
        xc, wqkvT, nullptr, qkv, QKVCOLS);

    // V transpose per head
    vtrans<<<dim3(NDIM / 32, DHEAD / 32, BDIM * HDIM), dim3(32, 8)>>>(qkv, vT);

    // Attention
    cudaFuncSetAttribute(attn_mma,
                         cudaFuncAttributeMaxDynamicSharedMemorySize, AS_TOTAL);
    attn_mma<<<dim3(NDIM / 128, BDIM * HDIM), 256, AS_TOTAL>>>(
        qkv, vT, attnP, padP, ctx);

    // Output projection + bias (full fp32 out)
    gemm_mma<true, false><<<dim3(CDIM / 128, MROWS / 128), 256, GS_TOTAL>>>(
        ctx, wprojT, bias, out, CDIM);
}

// round 5
// speedup vs baseline: 6.5535x; 1.6318x over previous
#include <cuda_runtime.h>
#include <cuda_fp16.h>
#include <cstdint>

// Problem constants
#define BDIM 4
#define NDIM 2048
#define CDIM 1024
#define HDIM 16
#define DHEAD 64
#define MROWS 8192
#define QKVCOLS 3072
#define KDIM 1024
#define NEGVAL (-10000000.0f)

// Scratch (device globals: allocation-free, graph-capturable)
__device__ __half g_qkvh[(size_t)MROWS * QKVCOLS];      // fp16 qkv
__device__ __half g_ctxh[(size_t)MROWS * CDIM];         // fp16 attention out
__device__ __half g_Xh[(size_t)MROWS * KDIM];           // fp16 input
__device__ __half g_WqkvTh[(size_t)QKVCOLS * KDIM];     // [N,K] fp16
__device__ __half g_WprojTh[(size_t)CDIM * KDIM];       // [N,K] fp16
__device__ __half g_vTh[(size_t)BDIM * HDIM * DHEAD * NDIM]; // V^T [bh][d][key]
__device__ unsigned long long g_attnP[(size_t)NDIM * (NDIM / 64)];
__device__ unsigned long long g_padP[BDIM * (NDIM / 64)];

// ---------------------------------------------------------------------------
// Helpers
// ---------------------------------------------------------------------------
__device__ __forceinline__ uint32_t smem_u32(const void* p) {
    uint32_t a;
    asm("{ .reg .u64 t; cvta.to.shared.u64 t, %1; cvt.u32.u64 %0, t; }"
        : "=r"(a) : "l"(p));
    return a;
}

__device__ __forceinline__ void ldm4(uint32_t* r, uint32_t addr) {
    asm volatile("ldmatrix.sync.aligned.m8n8.x4.shared.b16 {%0,%1,%2,%3}, [%4];"
                 : "=r"(r[0]), "=r"(r[1]), "=r"(r[2]), "=r"(r[3]) : "r"(addr));
}

__device__ __forceinline__ void mma16(float* d, const uint32_t* a,
                                      uint32_t b0, uint32_t b1) {
    asm volatile(
        "mma.sync.aligned.m16n8k16.row.col.f32.f16.f16.f32 "
        "{%0,%1,%2,%3},{%4,%5,%6,%7},{%8,%9},{%0,%1,%2,%3};"
        : "+f"(d[0]), "+f"(d[1]), "+f"(d[2]), "+f"(d[3])
        : "r"(a[0]), "r"(a[1]), "r"(a[2]), "r"(a[3]), "r"(b0), "r"(b1));
}

__device__ __forceinline__ void cpa16(uint32_t s, const void* g) {
    asm volatile("cp.async.cg.shared.global [%0], [%1], 16;" :: "r"(s), "l"(g));
}
#define CP_COMMIT() asm volatile("cp.async.commit_group;" ::: "memory")
#define CP_WAIT1()  asm volatile("cp.async.wait_group 1;" ::: "memory")

// ---------------------------------------------------------------------------
// Mask packing
// ---------------------------------------------------------------------------
__global__ __launch_bounds__(256) void pack_attn(
    const int* __restrict__ attn, unsigned long long* __restrict__ attnP)
{
    int w = blockIdx.x * 8 + (threadIdx.x >> 5);
    int lane = threadIdx.x & 31;
    int nq = w >> 5, kb = w & 31;
    const int* p = attn + (size_t)nq * NDIM + kb * 64;
    unsigned b0 = __ballot_sync(~0u, p[lane] > 0);
    unsigned b1 = __ballot_sync(~0u, p[lane + 32] > 0);
    if (lane == 0) attnP[w] = (unsigned long long)b0 | ((unsigned long long)b1 << 32);
}

__global__ __launch_bounds__(256) void pack_pad(
    const int* __restrict__ pad, unsigned long long* __restrict__ padP)
{
    int w = blockIdx.x * 8 + (threadIdx.x >> 5);
    int lane = threadIdx.x & 31;
    if (w < BDIM * 32) {
        int b = w >> 5, kb = w & 31;
        const int* p = pad + b * NDIM + kb * 64;
        unsigned b0 = __ballot_sync(~0u, p[lane] <= 0);
        unsigned b1 = __ballot_sync(~0u, p[lane + 32] <= 0);
        if (lane == 0) padP[w] = (unsigned long long)b0 | ((unsigned long long)b1 << 32);
    }
}

// ---------------------------------------------------------------------------
// fp16 conversion / transposes
// ---------------------------------------------------------------------------
__global__ __launch_bounds__(256) void cvt_f16_vec(
    const float* __restrict__ in, __half* __restrict__ out, int n4)
{
    int i = blockIdx.x * 256 + threadIdx.x;
    if (i < n4) {
        float4 v = ((const float4*)in)[i];
        __half2 h0 = __floats2half2_rn(v.x, v.y);
        __half2 h1 = __floats2half2_rn(v.z, v.w);
        ((uint2*)out)[i] = make_uint2(*(uint32_t*)&h0, *(uint32_t*)&h1);
    }
}

// out[n][k] = f16(in[k][n])
__global__ __launch_bounds__(256) void transpose32h(
    const float* __restrict__ in, __half* __restrict__ out, int rows, int cols)
{
    __shared__ float t[32][33];
    const int bx = blockIdx.x * 32, by = blockIdx.y * 32;
    const int txl = threadIdx.x, tyl = threadIdx.y;
#pragma unroll
    for (int i = tyl; i < 32; i += 8)
        t[i][txl] = in[(size_t)(by + i) * cols + bx + txl];
    __syncthreads();
#pragma unroll
    for (int i = tyl; i < 32; i += 8)
        out[(size_t)(bx + i) * rows + by + txl] = __float2half_rn(t[txl][i]);
}

// V^T: vT[bh][d][key] = qkvh[b, key, 2048 + h*64 + d]
__global__ __launch_bounds__(256) void vtrans_h(
    const __half* __restrict__ qkv, __half* __restrict__ vT)
{
    __shared__ __half t[32][36];
    const int key0 = blockIdx.x * 32, d0 = blockIdx.y * 32;
    const int bh = blockIdx.z;
    const int b = bh >> 4, h = bh & 15;
    const int txl = threadIdx.x, tyl = threadIdx.y;
    const __half* src = qkv + (size_t)b * NDIM * QKVCOLS + 2 * CDIM + h * DHEAD;
#pragma unroll
    for (int i = tyl; i < 32; i += 8)
        t[i][txl] = src[(size_t)(key0 + i) * QKVCOLS + d0 + txl];
    __syncthreads();
    __half* dst = vT + (size_t)bh * DHEAD * NDIM;
#pragma unroll
    for (int i = tyl; i < 32; i += 8)
        dst[(size_t)(d0 + i) * NDIM + key0 + txl] = t[txl][i];
}

// ---------------------------------------------------------------------------
// fp16 mma GEMM: C[M,Ncols] = A[M,1024] @ Bt[Ncols,1024]^T (+bias)
// 128x128 tile, BK=64 (128B swizzled rows), 3-stage cp.async, 8 warps.
// ---------------------------------------------------------------------------
#define GS_STAGE 32768
#define GS_TOTAL (3 * GS_STAGE)   // 96 KB

template <bool HAS_BIAS, bool OUT_HALF>
__global__ __launch_bounds__(256, 2) void gemm_mma_h(
    const __half* __restrict__ A, const __half* __restrict__ Bt,
    const float* __restrict__ bias, void* __restrict__ Cout, int Ncols)
{
    extern __shared__ char smem[];
    const uint32_t sb = smem_u32(smem);
    const int tid = threadIdx.x, lane = tid & 31, wid = tid >> 5;
    const int mw = wid >> 2, nw = wid & 3;
    const int n0 = blockIdx.x * 128, m0 = blockIdx.y * 128;

    const __half* Ag = A + (size_t)m0 * KDIM;
    const __half* Bg = Bt + (size_t)n0 * KDIM;

    float c[4][4][4];
#pragma unroll
    for (int i = 0; i < 4; ++i)
#pragma unroll
        for (int j = 0; j < 4; ++j)
#pragma unroll
            for (int k = 0; k < 4; ++k) c[i][j][k] = 0.0f;

    auto loadChunk = [&](int ch) {
        const int s = ch % 3;
        const uint32_t aB = sb + s * GS_STAGE, bB = aB + 16384;
        const int kc = ch * 64;
#pragma unroll
        for (int i = 0; i < 4; ++i) {
            int idx = i * 256 + tid;
            int r = idx >> 3, c16 = idx & 7;
            uint32_t so = (uint32_t)(r * 128 + ((c16 * 16) ^ ((r & 7) << 4)));
            cpa16(aB + so, Ag + (size_t)r * KDIM + kc + c16 * 8);
            cpa16(bB + so, Bg + (size_t)r * KDIM + kc + c16 * 8);
        }
    };

    loadChunk(0); CP_COMMIT();
    loadChunk(1); CP_COMMIT();

    const int lrow = lane & 15;
    const int hib = (lane >> 4) * 16;

    for (int ch = 0; ch < 16; ++ch) {
        CP_WAIT1();
        __syncthreads();
        if (ch < 14) loadChunk(ch + 2);
        CP_COMMIT();

        const int s = ch % 3;
        const uint32_t aB = sb + s * GS_STAGE, bB = aB + 16384;
#pragma unroll
        for (int ks = 0; ks < 4; ++ks) {
            const int cb = ks * 32 + hib;
            uint32_t a[4][4];
#pragma unroll
            for (int mf = 0; mf < 4; ++mf) {
                int r = mw * 64 + mf * 16 + lrow;
                ldm4(a[mf], aB + r * 128 + (cb ^ ((r & 7) << 4)));
            }
            uint32_t bfr[2][4];
#pragma unroll
            for (int bf2 = 0; bf2 < 2; ++bf2) {
                int r = nw * 32 + bf2 * 16 + lrow;
                ldm4(bfr[bf2], bB + r * 128 + (cb ^ ((r & 7) << 4)));
            }
#pragma unroll
            for (int mf = 0; mf < 4; ++mf)
#pragma unroll
                for (int nf = 0; nf < 4; ++nf)
                    mma16(c[mf][nf], a[mf], bfr[nf >> 1][nf & 1], bfr[nf >> 1][(nf & 1) + 2]);
        }
    }

    const int g = lane >> 2, tig = lane & 3;
#pragma unroll
    for (int mf = 0; mf < 4; ++mf) {
        int r0 = m0 + mw * 64 + mf * 16 + g;
#pragma unroll
        for (int nf = 0; nf < 4; ++nf) {
            int col = n0 + nw * 32 + nf * 8 + tig * 2;
            if (OUT_HALF) {
                __half* Ch = (__half*)Cout;
                __half2 h0 = __floats2half2_rn(c[mf][nf][0], c[mf][nf][1]);
                __half2 h1 = __floats2half2_rn(c[mf][nf][2], c[mf][nf][3]);
                *(__half2*)(Ch + (size_t)r0 * Ncols + col) = h0;
                *(__half2*)(Ch + (size_t)(r0 + 8) * Ncols + col) = h1;
            } else {
                float* Cf = (float*)Cout;
                float b0 = 0.0f, b1 = 0.0f;
                if (HAS_BIAS) { b0 = bias[col]; b1 = bias[col + 1]; }
                *(float2*)(Cf + (size_t)r0 * Ncols + col) =
                    make_float2(c[mf][nf][0] + b0, c[mf][nf][1] + b1);
                *(float2*)(Cf + (size_t)(r0 + 8) * Ncols + col) =
                    make_float2(c[mf][nf][2] + b0, c[mf][nf][3] + b1);
            }
        }
    }
}

// ---------------------------------------------------------------------------
// Flash attention, fp16 mma. CTA: 128 q-rows x (b,h), 256 thr, 8 warps.
// Warp: 16 q x 64 keys. smem: QP 16KB | K0,K1,V0,V1 8KB each = 48KB.
// ---------------------------------------------------------------------------
#define AS_QP 0
#define AS_K0 16384
#define AS_K1 24576
#define AS_V0 32768
#define AS_V1 40960
#define AS_TOTAL 49152

__global__ __launch_bounds__(256, 2) void attn_mma_h(
    const __half* __restrict__ qkv, const __half* __restrict__ vT,
    const unsigned long long* __restrict__ attnP,
    const unsigned long long* __restrict__ padP,
    __half* __restrict__ ctx)
{
    extern __shared__ char smem[];
    const uint32_t sb = smem_u32(smem);
    const int tid = threadIdx.x, lane = tid & 31, wid = tid >> 5;
    const int g = lane >> 2, tig = lane & 3;
    const int lrow = lane & 15;
    const int hib = (lane >> 4) * 16;

    const int n0 = blockIdx.x * 128;
    const int bh = blockIdx.y;
    const int b = bh >> 4, h = bh & 15;

    const __half* qbase = qkv + (size_t)(b * NDIM + n0) * QKVCOLS + h * DHEAD;
    const __half* kbase = qkv + (size_t)b * NDIM * QKVCOLS + CDIM + h * DHEAD;
    const __half* vtb   = vT + (size_t)bh * DHEAD * NDIM;

    const uint32_t sK[2] = {sb + AS_K0, sb + AS_K1};
    const uint32_t sV[2] = {sb + AS_V0, sb + AS_V1};

    auto loadKV = [&](int kt, int bf) {
#pragma unroll
        for (int i = 0; i < 2; ++i) {
            int idx = i * 256 + tid;
            int r = idx >> 3, c16 = idx & 7;
            uint32_t so = (uint32_t)(r * 128 + ((c16 * 16) ^ ((r & 7) << 4)));
            cpa16(sK[bf] + so, kbase + (size_t)(kt * 64 + r) * QKVCOLS + c16 * 8);
            cpa16(sV[bf] + so, vtb + (size_t)r * NDIM + kt * 64 + c16 * 8);
        }
    };

    // Q tile + first K/V
#pragma unroll
    for (int i = 0; i < 4; ++i) {
        int idx = i * 256 + tid;
        int r = idx >> 3, c16 = idx & 7;
        uint32_t so = (uint32_t)(r * 128 + ((c16 * 16) ^ ((r & 7) << 4)));
        cpa16(sb + AS_QP + so, qbase + (size_t)r * QKVCOLS + c16 * 8);
    }
    loadKV(0, 0);
    CP_COMMIT();

    float oc[8][4];
#pragma unroll
    for (int f = 0; f < 8; ++f)
#pragma unroll
        for (int j = 0; j < 4; ++j) oc[f][j] = 0.0f;
    float m0r = -1e30f, m1r = -1e30f, l0 = 0.0f, l1 = 0.0f;
    uint32_t qf[4][4];

    const int qrow0 = n0 + wid * 16 + g;
    const float scale = 0.125f;

    for (int kt = 0; kt < NDIM / 64; ++kt) {
        __syncthreads();
        if (kt < 31) loadKV(kt + 1, (kt + 1) & 1);
        CP_COMMIT();
        CP_WAIT1();
        __syncthreads();

        if (kt == 0) {
#pragma unroll
            for (int ks = 0; ks < 4; ++ks) {
                int r = wid * 16 + lrow;
                ldm4(qf[ks], sb + AS_QP + r * 128 + ((ks * 32 + hib) ^ ((r & 7) << 4)));
            }
            __syncwarp();
        }

        const uint32_t kB = sK[kt & 1], vB = sV[kt & 1];

        // S = Q @ K^T
        float sc[8][4];
#pragma unroll
        for (int f = 0; f < 8; ++f)
#pragma unroll
            for (int j = 0; j < 4; ++j) sc[f][j] = 0.0f;

#pragma unroll
        for (int ks = 0; ks < 4; ++ks) {
            const int cb = ks * 32 + hib;
#pragma unroll
            for (int f = 0; f < 4; ++f) {
                uint32_t bf[4];
                int rk = f * 16 + lrow;
                ldm4(bf, kB + rk * 128 + (cb ^ ((rk & 7) << 4)));
                mma16(sc[f * 2 + 0], qf[ks], bf[0], bf[2]);
                mma16(sc[f * 2 + 1], qf[ks], bf[1], bf[3]);
            }
        }

        // Masks
        const unsigned long long pw = padP[b * 32 + kt];
        const unsigned long long a0w = attnP[(size_t)qrow0 * 32 + kt] & pw;
        const unsigned long long a1w = attnP[(size_t)(qrow0 + 8) * 32 + kt] & pw;
#pragma unroll
        for (int f = 0; f < 8; ++f) {
            int j0 = f * 8 + tig * 2;
            sc[f][0] = ((a0w >> j0) & 1ull)       ? sc[f][0] * scale : NEGVAL;
            sc[f][1] = ((a0w >> (j0 + 1)) & 1ull) ? sc[f][1] * scale : NEGVAL;
            sc[f][2] = ((a1w >> j0) & 1ull)       ? sc[f][2] * scale : NEGVAL;
            sc[f][3] = ((a1w >> (j0 + 1)) & 1ull) ? sc[f][3] * scale : NEGVAL;
        }

        // Online softmax (row = 4-lane group)
        float mb0 = sc[0][0], mb1 = sc[0][2];
#pragma unroll
        for (int f = 0; f < 8; ++f) {
            mb0 = fmaxf(mb0, fmaxf(sc[f][0], sc[f][1]));
            mb1 = fmaxf(mb1, fmaxf(sc[f][2], sc[f][3]));
        }
        mb0 = fmaxf(mb0, __shfl_xor_sync(~0u, mb0, 1));
        mb0 = fmaxf(mb0, __shfl_xor_sync(~0u, mb0, 2));
        mb1 = fmaxf(mb1, __shfl_xor_sync(~0u, mb1, 1));
        mb1 = fmaxf(mb1, __shfl_xor_sync(~0u, mb1, 2));

        const float mn0 = fmaxf(m0r, mb0), mn1 = fmaxf(m1r, mb1);
        const float corr0 = __expf(m0r - mn0), corr1 = __expf(m1r - mn1);
        m0r = mn0; m1r = mn1;

        // exp, round to fp16 (matches P fragment), sum, store P to smem
        const int rl0 = wid * 16 + g, rl1 = rl0 + 8;
        float s0 = 0.0f, s1 = 0.0f;
#pragma unroll
        for (int f = 0; f < 8; ++f) {
            __half2 h0 = __floats2half2_rn(__expf(sc[f][0] - mn0), __expf(sc[f][1] - mn0));
            __half2 h1 = __floats2half2_rn(__expf(sc[f][2] - mn1), __expf(sc[f][3] - mn1));
            float2 f0 = __half22float2(h0);
            float2 f1 = __half22float2(h1);
            s0 += f0.x + f0.y;
            s1 += f1.x + f1.y;
            int cb2 = (f * 8 + tig * 2) * 2;
            *(__half2*)(smem + AS_QP + rl0 * 128 + (cb2 ^ ((rl0 & 7) << 4))) = h0;
            *(__half2*)(smem + AS_QP + rl1 * 128 + (cb2 ^ ((rl1 & 7) << 4))) = h1;
        }
        s0 += __shfl_xor_sync(~0u, s0, 1);
        s0 += __shfl_xor_sync(~0u, s0, 2);
        s1 += __shfl_xor_sync(~0u, s1, 1);
        s1 += __shfl_xor_sync(~0u, s1, 2);
        l0 = l0 * corr0 + s0;
        l1 = l1 * corr1 + s1;
#pragma unroll
        for (int f = 0; f < 8; ++f) {
            oc[f][0] *= corr0; oc[f][1] *= corr0;
            oc[f][2] *= corr1; oc[f][3] *= corr1;
        }
        __syncwarp();

        // O += P @ V  (V^T tile rows = d, cols = keys)
#pragma unroll
        for (int ks = 0; ks < 4; ++ks) {
            const int cb = ks * 32 + hib;
            uint32_t a[4];
            {
                int r = wid * 16 + lrow;
                ldm4(a, sb + AS_QP + r * 128 + (cb ^ ((r & 7) << 4)));
            }
#pragma unroll
            for (int f = 0; f < 4; ++f) {
                uint32_t bf[4];
                int rd = f * 16 + lrow;
                ldm4(bf, vB + rd * 128 + (cb ^ ((rd & 7) << 4)));
                mma16(oc[f * 2 + 0], a, bf[0], bf[2]);
                mma16(oc[f * 2 + 1], a, bf[1], bf[3]);
            }
        }
    }

    // Epilogue: normalize, store fp16 ctx
    const float inv0 = 1.0f / l0, inv1 = 1.0f / l1;
#pragma unroll
    for (int f = 0; f < 8; ++f) {
        int col = h * DHEAD + f * 8 + tig * 2;
        __half2 h0 = __floats2half2_rn(oc[f][0] * inv0, oc[f][1] * inv0);
        __half2 h1 = __floats2half2_rn(oc[f][2] * inv1, oc[f][3] * inv1);
        *(__half2*)(ctx + (size_t)(b * NDIM + qrow0) * CDIM + col) = h0;
        *(__half2*)(ctx + (size_t)(b * NDIM + qrow0 + 8) * CDIM + col) = h1;
    }
}

// ---------------------------------------------------------------------------
extern "C" void kernel_launch(void* const* d_in, const int* in_sizes, int n_in,
                              void* d_out, int out_size)
{
    const float* X       = (const float*)d_in[0];
    const int* attn_mask = (const int*)d_in[1];
    const int* pad_mask  = (const int*)d_in[2];
    const float* Wqkv    = (const float*)d_in[3];
    const float* Wproj   = (const float*)d_in[4];
    const float* bias    = (const float*)d_in[5];
    float* out           = (float*)d_out;

    __half *qkvh, *ctxh, *xh, *wqkvTh, *wprojTh, *vTh;
    unsigned long long *attnP, *padP;
    cudaGetSymbolAddress((void**)&qkvh, g_qkvh);
    cudaGetSymbolAddress((void**)&ctxh, g_ctxh);
    cudaGetSymbolAddress((void**)&xh, g_Xh);
    cudaGetSymbolAddress((void**)&wqkvTh, g_WqkvTh);
    cudaGetSymbolAddress((void**)&wprojTh, g_WprojTh);
    cudaGetSymbolAddress((void**)&vTh, g_vTh);
    cudaGetSymbolAddress((void**)&attnP, g_attnP);
    cudaGetSymbolAddress((void**)&padP, g_padP);

    // Prep
    pack_attn<<<(NDIM * 32) / 8, 256>>>(attn_mask, attnP);
    pack_pad<<<16, 256>>>(pad_mask, padP);
    cvt_f16_vec<<<(MROWS * KDIM / 4) / 256, 256>>>(X, xh, MROWS * KDIM / 4);
    transpose32h<<<dim3(QKVCOLS / 32, KDIM / 32), dim3(32, 8)>>>(Wqkv, wqkvTh, KDIM, QKVCOLS);
    transpose32h<<<dim3(CDIM / 32, KDIM / 32), dim3(32, 8)>>>(Wproj, wprojTh, KDIM, CDIM);

    // QKV projection -> fp16
    cudaFuncSetAttribute(gemm_mma_h<false, true>,
                         cudaFuncAttributeMaxDynamicSharedMemorySize, GS_TOTAL);
    cudaFuncSetAttribute(gemm_mma_h<true, false>,
                         cudaFuncAttributeMaxDynamicSharedMemorySize, GS_TOTAL);
    gemm_mma_h<false, true><<<dim3(QKVCOLS / 128, MROWS / 128), 256, GS_TOTAL>>>(
        xh, wqkvTh, nullptr, qkvh, QKVCOLS);

    // V^T per head
    vtrans_h<<<dim3(NDIM / 32, DHEAD / 32, BDIM * HDIM), dim3(32, 8)>>>(qkvh, vTh);

    // Attention
    cudaFuncSetAttribute(attn_mma_h,
                         cudaFuncAttributeMaxDynamicSharedMemorySize, AS_TOTAL);
    attn_mma_h<<<dim3(NDIM / 128, BDIM * HDIM), 256, AS_TOTAL>>>(
        qkvh, vTh, attnP, padP, ctxh);

    // Output projection + bias -> fp32
    gemm_mma_h<true, false><<<dim3(CDIM / 128, MROWS / 128), 256, GS_TOTAL>>>(
        ctxh, wprojTh, bias, out, CDIM);
}

// round 6
// speedup vs baseline: 7.0412x; 1.0744x over previous
#include <cuda_runtime.h>
#include <cuda_fp16.h>
#include <cstdint>

// Problem constants
#define BDIM 4
#define NDIM 2048
#define CDIM 1024
#define HDIM 16
#define DHEAD 64
#define MROWS 8192
#define QKVCOLS 3072
#define KDIM 1024
#define NEGVAL (-10000000.0f)

// Scratch (device globals: allocation-free, graph-capturable)
__device__ __half g_qkvh[(size_t)MROWS * QKVCOLS];
__device__ __half g_ctxh[(size_t)MROWS * CDIM];
__device__ __half g_Xh[(size_t)MROWS * KDIM];
__device__ __half g_WqkvTh[(size_t)QKVCOLS * KDIM];
__device__ __half g_WprojTh[(size_t)CDIM * KDIM];
__device__ __half g_vTh[(size_t)BDIM * HDIM * DHEAD * NDIM];
__device__ unsigned long long g_attnP[(size_t)NDIM * (NDIM / 64)];
__device__ unsigned long long g_padP[BDIM * (NDIM / 64)];

// ---------------------------------------------------------------------------
// Helpers
// ---------------------------------------------------------------------------
__device__ __forceinline__ uint32_t smem_u32(const void* p) {
    uint32_t a;
    asm("{ .reg .u64 t; cvta.to.shared.u64 t, %1; cvt.u32.u64 %0, t; }"
        : "=r"(a) : "l"(p));
    return a;
}

__device__ __forceinline__ void ldm4(uint32_t* r, uint32_t addr) {
    asm volatile("ldmatrix.sync.aligned.m8n8.x4.shared.b16 {%0,%1,%2,%3}, [%4];"
                 : "=r"(r[0]), "=r"(r[1]), "=r"(r[2]), "=r"(r[3]) : "r"(addr));
}

__device__ __forceinline__ void mma16(float* d, const uint32_t* a,
                                      uint32_t b0, uint32_t b1) {
    asm volatile(
        "mma.sync.aligned.m16n8k16.row.col.f32.f16.f16.f32 "
        "{%0,%1,%2,%3},{%4,%5,%6,%7},{%8,%9},{%0,%1,%2,%3};"
        : "+f"(d[0]), "+f"(d[1]), "+f"(d[2]), "+f"(d[3])
        : "r"(a[0]), "r"(a[1]), "r"(a[2]), "r"(a[3]), "r"(b0), "r"(b1));
}

__device__ __forceinline__ void cpa16(uint32_t s, const void* g) {
    asm volatile("cp.async.cg.shared.global [%0], [%1], 16;" :: "r"(s), "l"(g));
}
#define CP_COMMIT() asm volatile("cp.async.commit_group;" ::: "memory")
#define CP_WAIT1()  asm volatile("cp.async.wait_group 1;" ::: "memory")

// ---------------------------------------------------------------------------
// Mask packing
// ---------------------------------------------------------------------------
__global__ __launch_bounds__(256) void pack_attn(
    const int* __restrict__ attn, unsigned long long* __restrict__ attnP)
{
    int w = blockIdx.x * 8 + (threadIdx.x >> 5);
    int lane = threadIdx.x & 31;
    int nq = w >> 5, kb = w & 31;
    const int* p = attn + (size_t)nq * NDIM + kb * 64;
    unsigned b0 = __ballot_sync(~0u, p[lane] > 0);
    unsigned b1 = __ballot_sync(~0u, p[lane + 32] > 0);
    if (lane == 0) attnP[w] = (unsigned long long)b0 | ((unsigned long long)b1 << 32);
}

__global__ __launch_bounds__(256) void pack_pad(
    const int* __restrict__ pad, unsigned long long* __restrict__ padP)
{
    int w = blockIdx.x * 8 + (threadIdx.x >> 5);
    int lane = threadIdx.x & 31;
    if (w < BDIM * 32) {
        int b = w >> 5, kb = w & 31;
        const int* p = pad + b * NDIM + kb * 64;
        unsigned b0 = __ballot_sync(~0u, p[lane] <= 0);
        unsigned b1 = __ballot_sync(~0u, p[lane + 32] <= 0);
        if (lane == 0) padP[w] = (unsigned long long)b0 | ((unsigned long long)b1 << 32);
    }
}

// ---------------------------------------------------------------------------
// fp16 conversion / transposes
// ---------------------------------------------------------------------------
__global__ __launch_bounds__(256) void cvt_f16_vec(
    const float* __restrict__ in, __half* __restrict__ out, int n4)
{
    int i = blockIdx.x * 256 + threadIdx.x;
    if (i < n4) {
        float4 v = ((const float4*)in)[i];
        __half2 h0 = __floats2half2_rn(v.x, v.y);
        __half2 h1 = __floats2half2_rn(v.z, v.w);
        ((uint2*)out)[i] = make_uint2(*(uint32_t*)&h0, *(uint32_t*)&h1);
    }
}

__global__ __launch_bounds__(256) void transpose32h(
    const float* __restrict__ in, __half* __restrict__ out, int rows, int cols)
{
    __shared__ float t[32][33];
    const int bx = blockIdx.x * 32, by = blockIdx.y * 32;
    const int txl = threadIdx.x, tyl = threadIdx.y;
#pragma unroll
    for (int i = tyl; i < 32; i += 8)
        t[i][txl] = in[(size_t)(by + i) * cols + bx + txl];
    __syncthreads();
#pragma unroll
    for (int i = tyl; i < 32; i += 8)
        out[(size_t)(bx + i) * rows + by + txl] = __float2half_rn(t[txl][i]);
}

__global__ __launch_bounds__(256) void vtrans_h(
    const __half* __restrict__ qkv, __half* __restrict__ vT)
{
    __shared__ __half t[32][36];
    const int key0 = blockIdx.x * 32, d0 = blockIdx.y * 32;
    const int bh = blockIdx.z;
    const int b = bh >> 4, h = bh & 15;
    const int txl = threadIdx.x, tyl = threadIdx.y;
    const __half* src = qkv + (size_t)b * NDIM * QKVCOLS + 2 * CDIM + h * DHEAD;
#pragma unroll
    for (int i = tyl; i < 32; i += 8)
        t[i][txl] = src[(size_t)(key0 + i) * QKVCOLS + d0 + txl];
    __syncthreads();
    __half* dst = vT + (size_t)bh * DHEAD * NDIM;
#pragma unroll
    for (int i = tyl; i < 32; i += 8)
        dst[(size_t)(d0 + i) * NDIM + key0 + txl] = t[txl][i];
}

// ---------------------------------------------------------------------------
// fp16 mma GEMM: 128x128 CTA tile, 4 warps (2x2), warp tile 64x64.
// BK=64, 3-stage cp.async. 128 threads, 2 CTA/SM.
// ---------------------------------------------------------------------------
#define GS_STAGE 32768
#define GS_TOTAL (3 * GS_STAGE)   // 96 KB

template <bool HAS_BIAS, bool OUT_HALF>
__global__ __launch_bounds__(128, 2) void gemm_mma_h(
    const __half* __restrict__ A, const __half* __restrict__ Bt,
    const float* __restrict__ bias, void* __restrict__ Cout, int Ncols)
{
    extern __shared__ char smem[];
    const uint32_t sb = smem_u32(smem);
    const int tid = threadIdx.x, lane = tid & 31, wid = tid >> 5;
    const int mw = wid >> 1, nw = wid & 1;
    const int n0 = blockIdx.x * 128, m0 = blockIdx.y * 128;

    const __half* Ag = A + (size_t)m0 * KDIM;
    const __half* Bg = Bt + (size_t)n0 * KDIM;

    float c[4][8][4];
#pragma unroll
    for (int i = 0; i < 4; ++i)
#pragma unroll
        for (int j = 0; j < 8; ++j)
#pragma unroll
            for (int k = 0; k < 4; ++k) c[i][j][k] = 0.0f;

    auto loadChunk = [&](int ch) {
        const int s = ch % 3;
        const uint32_t aB = sb + s * GS_STAGE, bB = aB + 16384;
        const int kc = ch * 64;
#pragma unroll
        for (int i = 0; i < 8; ++i) {
            int idx = i * 128 + tid;
            int r = idx >> 3, c16 = idx & 7;
            uint32_t so = (uint32_t)(r * 128 + ((c16 * 16) ^ ((r & 7) << 4)));
            cpa16(aB + so, Ag + (size_t)r * KDIM + kc + c16 * 8);
            cpa16(bB + so, Bg + (size_t)r * KDIM + kc + c16 * 8);
        }
    };

    loadChunk(0); CP_COMMIT();
    loadChunk(1); CP_COMMIT();

    const int lrow = lane & 15;
    const int hib = (lane >> 4) * 16;

    for (int ch = 0; ch < 16; ++ch) {
        CP_WAIT1();
        __syncthreads();
        if (ch < 14) loadChunk(ch + 2);
        CP_COMMIT();

        const int s = ch % 3;
        const uint32_t aB = sb + s * GS_STAGE, bB = aB + 16384;
#pragma unroll
        for (int ks = 0; ks < 4; ++ks) {
            const int cb = ks * 32 + hib;
            uint32_t a[4][4];
#pragma unroll
            for (int mf = 0; mf < 4; ++mf) {
                int r = mw * 64 + mf * 16 + lrow;
                ldm4(a[mf], aB + r * 128 + (cb ^ ((r & 7) << 4)));
            }
            uint32_t bfr[4][4];
#pragma unroll
            for (int bf2 = 0; bf2 < 4; ++bf2) {
                int r = nw * 64 + bf2 * 16 + lrow;
                ldm4(bfr[bf2], bB + r * 128 + (cb ^ ((r & 7) << 4)));
            }
#pragma unroll
            for (int mf = 0; mf < 4; ++mf)
#pragma unroll
                for (int nf2 = 0; nf2 < 4; ++nf2) {
                    mma16(c[mf][nf2 * 2 + 0], a[mf], bfr[nf2][0], bfr[nf2][2]);
                    mma16(c[mf][nf2 * 2 + 1], a[mf], bfr[nf2][1], bfr[nf2][3]);
                }
        }
    }

    const int g = lane >> 2, tig = lane & 3;
#pragma unroll
    for (int mf = 0; mf < 4; ++mf) {
        int r0 = m0 + mw * 64 + mf * 16 + g;
#pragma unroll
        for (int nf = 0; nf < 8; ++nf) {
            int col = n0 + nw * 64 + nf * 8 + tig * 2;
            if (OUT_HALF) {
                __half* Ch = (__half*)Cout;
                __half2 h0 = __floats2half2_rn(c[mf][nf][0], c[mf][nf][1]);
                __half2 h1 = __floats2half2_rn(c[mf][nf][2], c[mf][nf][3]);
                *(__half2*)(Ch + (size_t)r0 * Ncols + col) = h0;
                *(__half2*)(Ch + (size_t)(r0 + 8) * Ncols + col) = h1;
            } else {
                float* Cf = (float*)Cout;
                float b0 = 0.0f, b1 = 0.0f;
                if (HAS_BIAS) { b0 = bias[col]; b1 = bias[col + 1]; }
                *(float2*)(Cf + (size_t)r0 * Ncols + col) =
                    make_float2(c[mf][nf][0] + b0, c[mf][nf][1] + b1);
                *(float2*)(Cf + (size_t)(r0 + 8) * Ncols + col) =
                    make_float2(c[mf][nf][2] + b0, c[mf][nf][3] + b1);
            }
        }
    }
}

// ---------------------------------------------------------------------------
// Flash attention, fp16 mma, register-direct P (no smem round-trip).
// CTA: 128 q-rows x (b,h), 256 thr, 8 warps. Warp: 16 q x 64 keys.
// smem: Q 16KB | K0,K1,V0,V1 8KB each = 48KB.
// ---------------------------------------------------------------------------
#define AS_Q 0
#define AS_K0 16384
#define AS_K1 24576
#define AS_V0 32768
#define AS_V1 40960
#define AS_TOTAL 49152

__global__ __launch_bounds__(256, 2) void attn_mma_h(
    const __half* __restrict__ qkv, const __half* __restrict__ vT,
    const unsigned long long* __restrict__ attnP,
    const unsigned long long* __restrict__ padP,
    __half* __restrict__ ctx)
{
    extern __shared__ char smem[];
    const uint32_t sb = smem_u32(smem);
    const int tid = threadIdx.x, lane = tid & 31, wid = tid >> 5;
    const int g = lane >> 2, tig = lane & 3;
    const int lrow = lane & 15;
    const int hib = (lane >> 4) * 16;

    const int n0 = blockIdx.x * 128;
    const int bh = blockIdx.y;
    const int b = bh >> 4, h = bh & 15;

    const __half* qbase = qkv + (size_t)(b * NDIM + n0) * QKVCOLS + h * DHEAD;
    const __half* kbase = qkv + (size_t)b * NDIM * QKVCOLS + CDIM + h * DHEAD;
    const __half* vtb   = vT + (size_t)bh * DHEAD * NDIM;

    const uint32_t sK[2] = {sb + AS_K0, sb + AS_K1};
    const uint32_t sV[2] = {sb + AS_V0, sb + AS_V1};

    auto loadKV = [&](int kt, int bf) {
#pragma unroll
        for (int i = 0; i < 2; ++i) {
            int idx = i * 256 + tid;
            int r = idx >> 3, c16 = idx & 7;
            uint32_t so = (uint32_t)(r * 128 + ((c16 * 16) ^ ((r & 7) << 4)));
            cpa16(sK[bf] + so, kbase + (size_t)(kt * 64 + r) * QKVCOLS + c16 * 8);
            cpa16(sV[bf] + so, vtb + (size_t)r * NDIM + kt * 64 + c16 * 8);
        }
    };

    // Q tile + first K/V
#pragma unroll
    for (int i = 0; i < 4; ++i) {
        int idx = i * 256 + tid;
        int r = idx >> 3, c16 = idx & 7;
        uint32_t so = (uint32_t)(r * 128 + ((c16 * 16) ^ ((r & 7) << 4)));
        cpa16(sb + AS_Q + so, qbase + (size_t)r * QKVCOLS + c16 * 8);
    }
    loadKV(0, 0);
    CP_COMMIT();

    float oc[8][4];
#pragma unroll
    for (int f = 0; f < 8; ++f)
#pragma unroll
        for (int j = 0; j < 4; ++j) oc[f][j] = 0.0f;
    float m0r = -1e30f, m1r = -1e30f, l0 = 0.0f, l1 = 0.0f;
    uint32_t qf[4][4];

    const int qrow0 = n0 + wid * 16 + g;
    const float scale = 0.125f;

    for (int kt = 0; kt < NDIM / 64; ++kt) {
        __syncthreads();
        if (kt < 31) loadKV(kt + 1, (kt + 1) & 1);
        CP_COMMIT();
        CP_WAIT1();
        __syncthreads();

        if (kt == 0) {
#pragma unroll
            for (int ks = 0; ks < 4; ++ks) {
                int r = wid * 16 + lrow;
                ldm4(qf[ks], sb + AS_Q + r * 128 + ((ks * 32 + hib) ^ ((r & 7) << 4)));
            }
        }

        const uint32_t kB = sK[kt & 1], vB = sV[kt & 1];

        // S = Q @ K^T
        float sc[8][4];
#pragma unroll
        for (int f = 0; f < 8; ++f)
#pragma unroll
            for (int j = 0; j < 4; ++j) sc[f][j] = 0.0f;

#pragma unroll
        for (int ks = 0; ks < 4; ++ks) {
            const int cb = ks * 32 + hib;
#pragma unroll
            for (int f = 0; f < 4; ++f) {
                uint32_t bf[4];
                int rk = f * 16 + lrow;
                ldm4(bf, kB + rk * 128 + (cb ^ ((rk & 7) << 4)));
                mma16(sc[f * 2 + 0], qf[ks], bf[0], bf[2]);
                mma16(sc[f * 2 + 1], qf[ks], bf[1], bf[3]);
            }
        }

        // Masks
        const unsigned long long pw = padP[b * 32 + kt];
        const unsigned long long a0w = attnP[(size_t)qrow0 * 32 + kt] & pw;
        const unsigned long long a1w = attnP[(size_t)(qrow0 + 8) * 32 + kt] & pw;
#pragma unroll
        for (int f = 0; f < 8; ++f) {
            int j0 = f * 8 + tig * 2;
            sc[f][0] = ((a0w >> j0) & 1ull)       ? sc[f][0] * scale : NEGVAL;
            sc[f][1] = ((a0w >> (j0 + 1)) & 1ull) ? sc[f][1] * scale : NEGVAL;
            sc[f][2] = ((a1w >> j0) & 1ull)       ? sc[f][2] * scale : NEGVAL;
            sc[f][3] = ((a1w >> (j0 + 1)) & 1ull) ? sc[f][3] * scale : NEGVAL;
        }

        // Online softmax (row = 4-lane group)
        float mb0 = sc[0][0], mb1 = sc[0][2];
#pragma unroll
        for (int f = 0; f < 8; ++f) {
            mb0 = fmaxf(mb0, fmaxf(sc[f][0], sc[f][1]));
            mb1 = fmaxf(mb1, fmaxf(sc[f][2], sc[f][3]));
        }
        mb0 = fmaxf(mb0, __shfl_xor_sync(~0u, mb0, 1));
        mb0 = fmaxf(mb0, __shfl_xor_sync(~0u, mb0, 2));
        mb1 = fmaxf(mb1, __shfl_xor_sync(~0u, mb1, 1));
        mb1 = fmaxf(mb1, __shfl_xor_sync(~0u, mb1, 2));

        const float mn0 = fmaxf(m0r, mb0), mn1 = fmaxf(m1r, mb1);
        const float corr0 = __expf(m0r - mn0), corr1 = __expf(m1r - mn1);
        m0r = mn0; m1r = mn1;

        // exp -> fp16 P fragments directly in registers.
        // C-fragment (row g / g+8, cols tig*2..+1) == A-fragment halves for PV mma.
        uint32_t pf[8][2];
        float s0 = 0.0f, s1 = 0.0f;
#pragma unroll
        for (int f = 0; f < 8; ++f) {
            __half2 h0 = __floats2half2_rn(__expf(sc[f][0] - mn0), __expf(sc[f][1] - mn0));
            __half2 h1 = __floats2half2_rn(__expf(sc[f][2] - mn1), __expf(sc[f][3] - mn1));
            pf[f][0] = *(uint32_t*)&h0;
            pf[f][1] = *(uint32_t*)&h1;
            float2 f0 = __half22float2(h0);
            float2 f1 = __half22float2(h1);
            s0 += f0.x + f0.y;
            s1 += f1.x + f1.y;
        }
        s0 += __shfl_xor_sync(~0u, s0, 1);
        s0 += __shfl_xor_sync(~0u, s0, 2);
        s1 += __shfl_xor_sync(~0u, s1, 1);
        s1 += __shfl_xor_sync(~0u, s1, 2);
        l0 = l0 * corr0 + s0;
        l1 = l1 * corr1 + s1;
#pragma unroll
        for (int f = 0; f < 8; ++f) {
            oc[f][0] *= corr0; oc[f][1] *= corr0;
            oc[f][2] *= corr1; oc[f][3] *= corr1;
        }

        // O += P @ V  (A = pf registers, B = V^T tile rows=d, cols=keys)
#pragma unroll
        for (int ks = 0; ks < 4; ++ks) {
            const int cb = ks * 32 + hib;
            uint32_t a[4] = {pf[2 * ks][0], pf[2 * ks][1],
                             pf[2 * ks + 1][0], pf[2 * ks + 1][1]};
#pragma unroll
            for (int f = 0; f < 4; ++f) {
                uint32_t bf[4];
                int rd = f * 16 + lrow;
                ldm4(bf, vB + rd * 128 + (cb ^ ((rd & 7) << 4)));
                mma16(oc[f * 2 + 0], a, bf[0], bf[2]);
                mma16(oc[f * 2 + 1], a, bf[1], bf[3]);
            }
        }
    }

    // Epilogue: normalize, store fp16 ctx
    const float inv0 = 1.0f / l0, inv1 = 1.0f / l1;
#pragma unroll
    for (int f = 0; f < 8; ++f) {
        int col = h * DHEAD + f * 8 + tig * 2;
        __half2 h0 = __floats2half2_rn(oc[f][0] * inv0, oc[f][1] * inv0);
        __half2 h1 = __floats2half2_rn(oc[f][2] * inv1, oc[f][3] * inv1);
        *(__half2*)(ctx + (size_t)(b * NDIM + qrow0) * CDIM + col) = h0;
        *(__half2*)(ctx + (size_t)(b * NDIM + qrow0 + 8) * CDIM + col) = h1;
    }
}

// ---------------------------------------------------------------------------
extern "C" void kernel_launch(void* const* d_in, const int* in_sizes, int n_in,
                              void* d_out, int out_size)
{
    const float* X       = (const float*)d_in[0];
    const int* attn_mask = (const int*)d_in[1];
    const int* pad_mask  = (const int*)d_in[2];
    const float* Wqkv    = (const float*)d_in[3];
    const float* Wproj   = (const float*)d_in[4];
    const float* bias    = (const float*)d_in[5];
    float* out           = (float*)d_out;

    __half *qkvh, *ctxh, *xh, *wqkvTh, *wprojTh, *vTh;
    unsigned long long *attnP, *padP;
    cudaGetSymbolAddress((void**)&qkvh, g_qkvh);
    cudaGetSymbolAddress((void**)&ctxh, g_ctxh);
    cudaGetSymbolAddress((void**)&xh, g_Xh);
    cudaGetSymbolAddress((void**)&wqkvTh, g_WqkvTh);
    cudaGetSymbolAddress((void**)&wprojTh, g_WprojTh);
    cudaGetSymbolAddress((void**)&vTh, g_vTh);
    cudaGetSymbolAddress((void**)&attnP, g_attnP);
    cudaGetSymbolAddress((void**)&padP, g_padP);

    // Prep
    pack_attn<<<(NDIM * 32) / 8, 256>>>(attn_mask, attnP);
    pack_pad<<<16, 256>>>(pad_mask, padP);
    cvt_f16_vec<<<(MROWS * KDIM / 4) / 256, 256>>>(X, xh, MROWS * KDIM / 4);
    transpose32h<<<dim3(QKVCOLS / 32, KDIM / 32), dim3(32, 8)>>>(Wqkv, wqkvTh, KDIM, QKVCOLS);
    transpose32h<<<dim3(CDIM / 32, KDIM / 32), dim3(32, 8)>>>(Wproj, wprojTh, KDIM, CDIM);

    // QKV projection -> fp16
    cudaFuncSetAttribute(gemm_mma_h<false, true>,
                         cudaFuncAttributeMaxDynamicSharedMemorySize, GS_TOTAL);
    cudaFuncSetAttribute(gemm_mma_h<true, false>,
                         cudaFuncAttributeMaxDynamicSharedMemorySize, GS_TOTAL);
    gemm_mma_h<false, true><<<dim3(QKVCOLS / 128, MROWS / 128), 128, GS_TOTAL>>>(
        xh, wqkvTh, nullptr, qkvh, QKVCOLS);

    // V^T per head
    vtrans_h<<<dim3(NDIM / 32, DHEAD / 32, BDIM * HDIM), dim3(32, 8)>>>(qkvh, vTh);

    // Attention
    cudaFuncSetAttribute(attn_mma_h,
                         cudaFuncAttributeMaxDynamicSharedMemorySize, AS_TOTAL);
    attn_mma_h<<<dim3(NDIM / 128, BDIM * HDIM), 256, AS_TOTAL>>>(
        qkvh, vTh, attnP, padP, ctxh);

    // Output projection + bias -> fp32
    gemm_mma_h<true, false><<<dim3(CDIM / 128, MROWS / 128), 128, GS_TOTAL>>>(
        ctxh, wprojTh, bias, out, CDIM);
}

// round 7
// speedup vs baseline: 8.4268x; 1.1968x over previous
#include <cuda_runtime.h>
#include <cuda_fp16.h>
#include <cstdint>

// Problem constants
#define BDIM 4
#define NDIM 2048
#define CDIM 1024
#define HDIM 16
#define DHEAD 64
#define MROWS 8192
#define QKVCOLS 3072
#define KDIM 1024
#define NEGVAL (-10000000.0f)
#define QSC 0.18033688011112042f   // 0.125 * log2(e)

// Scratch (device globals: allocation-free, graph-capturable)
__device__ __half g_qkvh[(size_t)MROWS * QKVCOLS];
__device__ __half g_ctxh[(size_t)MROWS * CDIM];
__device__ __half g_Xh[(size_t)MROWS * KDIM];
__device__ __half g_WqkvTh[(size_t)QKVCOLS * KDIM];
__device__ __half g_WprojTh[(size_t)CDIM * KDIM];
__device__ __half g_vTh[(size_t)BDIM * HDIM * DHEAD * NDIM];
__device__ unsigned long long g_attnP[(size_t)NDIM * (NDIM / 64)];
__device__ unsigned long long g_padP[BDIM * (NDIM / 64)];

// ---------------------------------------------------------------------------
// Helpers
// ---------------------------------------------------------------------------
__device__ __forceinline__ uint32_t smem_u32(const void* p) {
    uint32_t a;
    asm("{ .reg .u64 t; cvta.to.shared.u64 t, %1; cvt.u32.u64 %0, t; }"
        : "=r"(a) : "l"(p));
    return a;
}

__device__ __forceinline__ float ex2f(float x) {
    float y;
    asm("ex2.approx.f32 %0, %1;" : "=f"(y) : "f"(x));
    return y;
}

__device__ __forceinline__ void ldm4(uint32_t* r, uint32_t addr) {
    asm volatile("ldmatrix.sync.aligned.m8n8.x4.shared.b16 {%0,%1,%2,%3}, [%4];"
                 : "=r"(r[0]), "=r"(r[1]), "=r"(r[2]), "=r"(r[3]) : "r"(addr));
}

__device__ __forceinline__ void mma16(float* d, const uint32_t* a,
                                      uint32_t b0, uint32_t b1) {
    asm volatile(
        "mma.sync.aligned.m16n8k16.row.col.f32.f16.f16.f32 "
        "{%0,%1,%2,%3},{%4,%5,%6,%7},{%8,%9},{%0,%1,%2,%3};"
        : "+f"(d[0]), "+f"(d[1]), "+f"(d[2]), "+f"(d[3])
        : "r"(a[0]), "r"(a[1]), "r"(a[2]), "r"(a[3]), "r"(b0), "r"(b1));
}

__device__ __forceinline__ void cpa16(uint32_t s, const void* g) {
    asm volatile("cp.async.cg.shared.global [%0], [%1], 16;" :: "r"(s), "l"(g));
}
#define CP_COMMIT() asm volatile("cp.async.commit_group;" ::: "memory")
#define CP_WAIT1()  asm volatile("cp.async.wait_group 1;" ::: "memory")

// ---------------------------------------------------------------------------
// Mask packing
// ---------------------------------------------------------------------------
__global__ __launch_bounds__(256) void pack_attn(
    const int* __restrict__ attn, unsigned long long* __restrict__ attnP)
{
    int w = blockIdx.x * 8 + (threadIdx.x >> 5);
    int lane = threadIdx.x & 31;
    int nq = w >> 5, kb = w & 31;
    const int* p = attn + (size_t)nq * NDIM + kb * 64;
    unsigned b0 = __ballot_sync(~0u, p[lane] > 0);
    unsigned b1 = __ballot_sync(~0u, p[lane + 32] > 0);
    if (lane == 0) attnP[w] = (unsigned long long)b0 | ((unsigned long long)b1 << 32);
}

__global__ __launch_bounds__(256) void pack_pad(
    const int* __restrict__ pad, unsigned long long* __restrict__ padP)
{
    int w = blockIdx.x * 8 + (threadIdx.x >> 5);
    int lane = threadIdx.x & 31;
    if (w < BDIM * 32) {
        int b = w >> 5, kb = w & 31;
        const int* p = pad + b * NDIM + kb * 64;
        unsigned b0 = __ballot_sync(~0u, p[lane] <= 0);
        unsigned b1 = __ballot_sync(~0u, p[lane + 32] <= 0);
        if (lane == 0) padP[w] = (unsigned long long)b0 | ((unsigned long long)b1 << 32);
    }
}

// ---------------------------------------------------------------------------
// fp16 conversion / transposes
// ---------------------------------------------------------------------------
__global__ __launch_bounds__(256) void cvt_f16_vec(
    const float* __restrict__ in, __half* __restrict__ out, int n4)
{
    int i = blockIdx.x * 256 + threadIdx.x;
    if (i < n4) {
        float4 v = ((const float4*)in)[i];
        __half2 h0 = __floats2half2_rn(v.x, v.y);
        __half2 h1 = __floats2half2_rn(v.z, v.w);
        ((uint2*)out)[i] = make_uint2(*(uint32_t*)&h0, *(uint32_t*)&h1);
    }
}

__global__ __launch_bounds__(256) void transpose32h(
    const float* __restrict__ in, __half* __restrict__ out, int rows, int cols)
{
    __shared__ float t[32][33];
    const int bx = blockIdx.x * 32, by = blockIdx.y * 32;
    const int txl = threadIdx.x, tyl = threadIdx.y;
#pragma unroll
    for (int i = tyl; i < 32; i += 8)
        t[i][txl] = in[(size_t)(by + i) * cols + bx + txl];
    __syncthreads();
#pragma unroll
    for (int i = tyl; i < 32; i += 8)
        out[(size_t)(bx + i) * rows + by + txl] = __float2half_rn(t[txl][i]);
}

__global__ __launch_bounds__(256) void vtrans_h(
    const __half* __restrict__ qkv, __half* __restrict__ vT)
{
    __shared__ __half t[32][36];
    const int key0 = blockIdx.x * 32, d0 = blockIdx.y * 32;
    const int bh = blockIdx.z;
    const int b = bh >> 4, h = bh & 15;
    const int txl = threadIdx.x, tyl = threadIdx.y;
    const __half* src = qkv + (size_t)b * NDIM * QKVCOLS + 2 * CDIM + h * DHEAD;
#pragma unroll
    for (int i = tyl; i < 32; i += 8)
        t[i][txl] = src[(size_t)(key0 + i) * QKVCOLS + d0 + txl];
    __syncthreads();
    __half* dst = vT + (size_t)bh * DHEAD * NDIM;
#pragma unroll
    for (int i = tyl; i < 32; i += 8)
        dst[(size_t)(d0 + i) * NDIM + key0 + txl] = t[txl][i];
}

// ---------------------------------------------------------------------------
// fp16 mma GEMM: 128x128 CTA tile, 4 warps (2x2), warp tile 64x64.
// BK=64, 3-stage cp.async. 128 threads, 2 CTA/SM.
// QKV variant scales Q columns (n0 < 1024) by QSC before fp16 store.
// ---------------------------------------------------------------------------
#define GS_STAGE 32768
#define GS_TOTAL (3 * GS_STAGE)   // 96 KB

template <bool HAS_BIAS, bool OUT_HALF>
__global__ __launch_bounds__(128, 2) void gemm_mma_h(
    const __half* __restrict__ A, const __half* __restrict__ Bt,
    const float* __restrict__ bias, void* __restrict__ Cout, int Ncols)
{
    extern __shared__ char smem[];
    const uint32_t sb = smem_u32(smem);
    const int tid = threadIdx.x, lane = tid & 31, wid = tid >> 5;
    const int mw = wid >> 1, nw = wid & 1;
    const int n0 = blockIdx.x * 128, m0 = blockIdx.y * 128;

    const __half* Ag = A + (size_t)m0 * KDIM;
    const __half* Bg = Bt + (size_t)n0 * KDIM;

    float c[4][8][4];
#pragma unroll
    for (int i = 0; i < 4; ++i)
#pragma unroll
        for (int j = 0; j < 8; ++j)
#pragma unroll
            for (int k = 0; k < 4; ++k) c[i][j][k] = 0.0f;

    auto loadChunk = [&](int ch) {
        const int s = ch % 3;
        const uint32_t aB = sb + s * GS_STAGE, bB = aB + 16384;
        const int kc = ch * 64;
#pragma unroll
        for (int i = 0; i < 8; ++i) {
            int idx = i * 128 + tid;
            int r = idx >> 3, c16 = idx & 7;
            uint32_t so = (uint32_t)(r * 128 + ((c16 * 16) ^ ((r & 7) << 4)));
            cpa16(aB + so, Ag + (size_t)r * KDIM + kc + c16 * 8);
            cpa16(bB + so, Bg + (size_t)r * KDIM + kc + c16 * 8);
        }
    };

    loadChunk(0); CP_COMMIT();
    loadChunk(1); CP_COMMIT();

    const int lrow = lane & 15;
    const int hib = (lane >> 4) * 16;

    for (int ch = 0; ch < 16; ++ch) {
        CP_WAIT1();
        __syncthreads();
        if (ch < 14) loadChunk(ch + 2);
        CP_COMMIT();

        const int s = ch % 3;
        const uint32_t aB = sb + s * GS_STAGE, bB = aB + 16384;
#pragma unroll
        for (int ks = 0; ks < 4; ++ks) {
            const int cb = ks * 32 + hib;
            uint32_t a[4][4];
#pragma unroll
            for (int mf = 0; mf < 4; ++mf) {
                int r = mw * 64 + mf * 16 + lrow;
                ldm4(a[mf], aB + r * 128 + (cb ^ ((r & 7) << 4)));
            }
            uint32_t bfr[4][4];
#pragma unroll
            for (int bf2 = 0; bf2 < 4; ++bf2) {
                int r = nw * 64 + bf2 * 16 + lrow;
                ldm4(bfr[bf2], bB + r * 128 + (cb ^ ((r & 7) << 4)));
            }
#pragma unroll
            for (int mf = 0; mf < 4; ++mf)
#pragma unroll
                for (int nf2 = 0; nf2 < 4; ++nf2) {
                    mma16(c[mf][nf2 * 2 + 0], a[mf], bfr[nf2][0], bfr[nf2][2]);
                    mma16(c[mf][nf2 * 2 + 1], a[mf], bfr[nf2][1], bfr[nf2][3]);
                }
        }
    }

    const int g = lane >> 2, tig = lane & 3;
    const float qs = (OUT_HALF && n0 < CDIM) ? QSC : 1.0f;  // pre-scale Q cols
#pragma unroll
    for (int mf = 0; mf < 4; ++mf) {
        int r0 = m0 + mw * 64 + mf * 16 + g;
#pragma unroll
        for (int nf = 0; nf < 8; ++nf) {
            int col = n0 + nw * 64 + nf * 8 + tig * 2;
            if (OUT_HALF) {
                __half* Ch = (__half*)Cout;
                __half2 h0 = __floats2half2_rn(c[mf][nf][0] * qs, c[mf][nf][1] * qs);
                __half2 h1 = __floats2half2_rn(c[mf][nf][2] * qs, c[mf][nf][3] * qs);
                *(__half2*)(Ch + (size_t)r0 * Ncols + col) = h0;
                *(__half2*)(Ch + (size_t)(r0 + 8) * Ncols + col) = h1;
            } else {
                float* Cf = (float*)Cout;
                float b0 = 0.0f, b1 = 0.0f;
                if (HAS_BIAS) { b0 = bias[col]; b1 = bias[col + 1]; }
                *(float2*)(Cf + (size_t)r0 * Ncols + col) =
                    make_float2(c[mf][nf][0] + b0, c[mf][nf][1] + b1);
                *(float2*)(Cf + (size_t)(r0 + 8) * Ncols + col) =
                    make_float2(c[mf][nf][2] + b0, c[mf][nf][3] + b1);
            }
        }
    }
}

// ---------------------------------------------------------------------------
// Flash attention, fp16 mma. CTA: 128 q-rows, 128 thr, 4 warps.
// Warp: 32 q x 64 keys (K/V fragments reused across 2 q-row fragments).
// smem: Q 16KB | K0,K1,V0,V1 8KB each = 48KB. 2 CTA/SM.
// Q is pre-scaled by 0.125*log2e; softmax in exp2 domain.
// ---------------------------------------------------------------------------
#define AS_Q 0
#define AS_K0 16384
#define AS_K1 24576
#define AS_V0 32768
#define AS_V1 40960
#define AS_TOTAL 49152

__global__ __launch_bounds__(128, 2) void attn_mma_h(
    const __half* __restrict__ qkv, const __half* __restrict__ vT,
    const unsigned long long* __restrict__ attnP,
    const unsigned long long* __restrict__ padP,
    __half* __restrict__ ctx)
{
    extern __shared__ char smem[];
    const uint32_t sb = smem_u32(smem);
    const int tid = threadIdx.x, lane = tid & 31, wid = tid >> 5;
    const int g = lane >> 2, tig = lane & 3;
    const int lrow = lane & 15;
    const int hib = (lane >> 4) * 16;

    const int n0 = blockIdx.x * 128;
    const int bh = blockIdx.y;
    const int b = bh >> 4, h = bh & 15;

    const __half* qbase = qkv + (size_t)(b * NDIM + n0) * QKVCOLS + h * DHEAD;
    const __half* kbase = qkv + (size_t)b * NDIM * QKVCOLS + CDIM + h * DHEAD;
    const __half* vtb   = vT + (size_t)bh * DHEAD * NDIM;

    const uint32_t sK[2] = {sb + AS_K0, sb + AS_K1};
    const uint32_t sV[2] = {sb + AS_V0, sb + AS_V1};

    auto loadKV = [&](int kt, int bf) {
#pragma unroll
        for (int i = 0; i < 4; ++i) {
            int idx = i * 128 + tid;
            int r = idx >> 3, c16 = idx & 7;
            uint32_t so = (uint32_t)(r * 128 + ((c16 * 16) ^ ((r & 7) << 4)));
            cpa16(sK[bf] + so, kbase + (size_t)(kt * 64 + r) * QKVCOLS + c16 * 8);
            cpa16(sV[bf] + so, vtb + (size_t)r * NDIM + kt * 64 + c16 * 8);
        }
    };

    // Q tile (128 rows) + first K/V
#pragma unroll
    for (int i = 0; i < 8; ++i) {
        int idx = i * 128 + tid;
        int r = idx >> 3, c16 = idx & 7;
        uint32_t so = (uint32_t)(r * 128 + ((c16 * 16) ^ ((r & 7) << 4)));
        cpa16(sb + AS_Q + so, qbase + (size_t)r * QKVCOLS + c16 * 8);
    }
    loadKV(0, 0);
    CP_COMMIT();

    float oc[2][8][4];
#pragma unroll
    for (int mf = 0; mf < 2; ++mf)
#pragma unroll
        for (int f = 0; f < 8; ++f)
#pragma unroll
            for (int j = 0; j < 4; ++j) oc[mf][f][j] = 0.0f;
    float mS[4] = {-1e30f, -1e30f, -1e30f, -1e30f};
    float lS[4] = {0.0f, 0.0f, 0.0f, 0.0f};
    uint32_t qf[4][2][4];

    const int qrow0 = n0 + wid * 32 + g;   // row of (mf=0, hf=0)

    for (int kt = 0; kt < NDIM / 64; ++kt) {
        __syncthreads();
        if (kt < 31) loadKV(kt + 1, (kt + 1) & 1);
        CP_COMMIT();
        CP_WAIT1();
        __syncthreads();

        if (kt == 0) {
#pragma unroll
            for (int ks = 0; ks < 4; ++ks)
#pragma unroll
                for (int mf = 0; mf < 2; ++mf) {
                    int r = wid * 32 + mf * 16 + lrow;
                    ldm4(qf[ks][mf],
                         sb + AS_Q + r * 128 + ((ks * 32 + hib) ^ ((r & 7) << 4)));
                }
        }

        const uint32_t kB = sK[kt & 1], vB = sV[kt & 1];

        // S = Q @ K^T  (32q x 64k per warp; K frags shared across mf)
        float sc[2][8][4];
#pragma unroll
        for (int mf = 0; mf < 2; ++mf)
#pragma unroll
            for (int f = 0; f < 8; ++f)
#pragma unroll
                for (int j = 0; j < 4; ++j) sc[mf][f][j] = 0.0f;

#pragma unroll
        for (int ks = 0; ks < 4; ++ks) {
            const int cb = ks * 32 + hib;
#pragma unroll
            for (int f = 0; f < 4; ++f) {
                uint32_t bf[4];
                int rk = f * 16 + lrow;
                ldm4(bf, kB + rk * 128 + (cb ^ ((rk & 7) << 4)));
#pragma unroll
                for (int mf = 0; mf < 2; ++mf) {
                    mma16(sc[mf][f * 2 + 0], qf[ks][mf], bf[0], bf[2]);
                    mma16(sc[mf][f * 2 + 1], qf[ks][mf], bf[1], bf[3]);
                }
            }
        }

        // Masks (fast path when every bit passes)
        const unsigned long long pw = padP[b * 32 + kt];
        unsigned long long aw[2][2];
#pragma unroll
        for (int mf = 0; mf < 2; ++mf)
#pragma unroll
            for (int hf = 0; hf < 2; ++hf)
                aw[mf][hf] = attnP[(size_t)(qrow0 + mf * 16 + hf * 8) * 32 + kt] & pw;
        bool allpass = __all_sync(~0u,
            (aw[0][0] & aw[0][1] & aw[1][0] & aw[1][1]) == ~0ull);
        if (!allpass) {
#pragma unroll
            for (int mf = 0; mf < 2; ++mf)
#pragma unroll
                for (int f = 0; f < 8; ++f) {
                    int j0 = f * 8 + tig * 2;
                    sc[mf][f][0] = ((aw[mf][0] >> j0) & 1ull)       ? sc[mf][f][0] : NEGVAL;
                    sc[mf][f][1] = ((aw[mf][0] >> (j0 + 1)) & 1ull) ? sc[mf][f][1] : NEGVAL;
                    sc[mf][f][2] = ((aw[mf][1] >> j0) & 1ull)       ? sc[mf][f][2] : NEGVAL;
                    sc[mf][f][3] = ((aw[mf][1] >> (j0 + 1)) & 1ull) ? sc[mf][f][3] : NEGVAL;
                }
        }

        // Online softmax in exp2 domain; rows live in 4-lane groups
        float mn[4], corr[4];
#pragma unroll
        for (int mf = 0; mf < 2; ++mf) {
            float mb0 = sc[mf][0][0], mb1 = sc[mf][0][2];
#pragma unroll
            for (int f = 0; f < 8; ++f) {
                mb0 = fmaxf(mb0, fmaxf(sc[mf][f][0], sc[mf][f][1]));
                mb1 = fmaxf(mb1, fmaxf(sc[mf][f][2], sc[mf][f][3]));
            }
            mb0 = fmaxf(mb0, __shfl_xor_sync(~0u, mb0, 1));
            mb0 = fmaxf(mb0, __shfl_xor_sync(~0u, mb0, 2));
            mb1 = fmaxf(mb1, __shfl_xor_sync(~0u, mb1, 1));
            mb1 = fmaxf(mb1, __shfl_xor_sync(~0u, mb1, 2));
            mn[mf * 2 + 0] = fmaxf(mS[mf * 2 + 0], mb0);
            mn[mf * 2 + 1] = fmaxf(mS[mf * 2 + 1], mb1);
        }
        bool nochange = (mn[0] == mS[0]) & (mn[1] == mS[1]) &
                        (mn[2] == mS[2]) & (mn[3] == mS[3]);
        bool skipc = __all_sync(~0u, nochange);
        if (!skipc) {
#pragma unroll
            for (int q = 0; q < 4; ++q) corr[q] = ex2f(mS[q] - mn[q]);
#pragma unroll
            for (int mf = 0; mf < 2; ++mf)
#pragma unroll
                for (int f = 0; f < 8; ++f) {
                    oc[mf][f][0] *= corr[mf * 2];     oc[mf][f][1] *= corr[mf * 2];
                    oc[mf][f][2] *= corr[mf * 2 + 1]; oc[mf][f][3] *= corr[mf * 2 + 1];
                }
#pragma unroll
            for (int q = 0; q < 4; ++q) lS[q] *= corr[q];
        }
#pragma unroll
        for (int q = 0; q < 4; ++q) mS[q] = mn[q];

        // p = 2^(s - m) -> fp16 fragments in registers
        uint32_t pf[2][8][2];
        float sum[4] = {0.0f, 0.0f, 0.0f, 0.0f};
#pragma unroll
        for (int mf = 0; mf < 2; ++mf)
#pragma unroll
            for (int f = 0; f < 8; ++f) {
                __half2 h0 = __floats2half2_rn(ex2f(sc[mf][f][0] - mn[mf * 2]),
                                               ex2f(sc[mf][f][1] - mn[mf * 2]));
                __half2 h1 = __floats2half2_rn(ex2f(sc[mf][f][2] - mn[mf * 2 + 1]),
                                               ex2f(sc[mf][f][3] - mn[mf * 2 + 1]));
                pf[mf][f][0] = *(uint32_t*)&h0;
                pf[mf][f][1] = *(uint32_t*)&h1;
                float2 f0 = __half22float2(h0);
                float2 f1 = __half22float2(h1);
                sum[mf * 2 + 0] += f0.x + f0.y;
                sum[mf * 2 + 1] += f1.x + f1.y;
            }
#pragma unroll
        for (int q = 0; q < 4; ++q) {
            sum[q] += __shfl_xor_sync(~0u, sum[q], 1);
            sum[q] += __shfl_xor_sync(~0u, sum[q], 2);
            lS[q] += sum[q];
        }

        // O += P @ V  (V frags shared across mf)
#pragma unroll
        for (int ks = 0; ks < 4; ++ks) {
            const int cb = ks * 32 + hib;
#pragma unroll
            for (int f = 0; f < 4; ++f) {
                uint32_t bf[4];
                int rd = f * 16 + lrow;
                ldm4(bf, vB + rd * 128 + (cb ^ ((rd & 7) << 4)));
#pragma unroll
                for (int mf = 0; mf < 2; ++mf) {
                    uint32_t a[4] = {pf[mf][2 * ks][0], pf[mf][2 * ks][1],
                                     pf[mf][2 * ks + 1][0], pf[mf][2 * ks + 1][1]};
                    mma16(oc[mf][f * 2 + 0], a, bf[0], bf[2]);
                    mma16(oc[mf][f * 2 + 1], a, bf[1], bf[3]);
                }
            }
        }
    }

    // Epilogue: normalize, store fp16 ctx
#pragma unroll
    for (int mf = 0; mf < 2; ++mf) {
        const float inv0 = 1.0f / lS[mf * 2], inv1 = 1.0f / lS[mf * 2 + 1];
        const int r0 = b * NDIM + qrow0 + mf * 16;
#pragma unroll
        for (int f = 0; f < 8; ++f) {
            int col = h * DHEAD + f * 8 + tig * 2;
            __half2 h0 = __floats2half2_rn(oc[mf][f][0] * inv0, oc[mf][f][1] * inv0);
            __half2 h1 = __floats2half2_rn(oc[mf][f][2] * inv1, oc[mf][f][3] * inv1);
            *(__half2*)(ctx + (size_t)r0 * CDIM + col) = h0;
            *(__half2*)(ctx + (size_t)(r0 + 8) * CDIM + col) = h1;
        }
    }
}

// ---------------------------------------------------------------------------
extern "C" void kernel_launch(void* const* d_in, const int* in_sizes, int n_in,
                              void* d_out, int out_size)
{
    const float* X       = (const float*)d_in[0];
    const int* attn_mask = (const int*)d_in[1];
    const int* pad_mask  = (const int*)d_in[2];
    const float* Wqkv    = (const float*)d_in[3];
    const float* Wproj   = (const float*)d_in[4];
    const float* bias    = (const float*)d_in[5];
    float* out           = (float*)d_out;

    __half *qkvh, *ctxh, *xh, *wqkvTh, *wprojTh, *vTh;
    unsigned long long *attnP, *padP;
    cudaGetSymbolAddress((void**)&qkvh, g_qkvh);
    cudaGetSymbolAddress((void**)&ctxh, g_ctxh);
    cudaGetSymbolAddress((void**)&xh, g_Xh);
    cudaGetSymbolAddress((void**)&wqkvTh, g_WqkvTh);
    cudaGetSymbolAddress((void**)&wprojTh, g_WprojTh);
    cudaGetSymbolAddress((void**)&vTh, g_vTh);
    cudaGetSymbolAddress((void**)&attnP, g_attnP);
    cudaGetSymbolAddress((void**)&padP, g_padP);

    // Prep
    pack_attn<<<(NDIM * 32) / 8, 256>>>(attn_mask, attnP);
    pack_pad<<<16, 256>>>(pad_mask, padP);
    cvt_f16_vec<<<(MROWS * KDIM / 4) / 256, 256>>>(X, xh, MROWS * KDIM / 4);
    transpose32h<<<dim3(QKVCOLS / 32, KDIM / 32), dim3(32, 8)>>>(Wqkv, wqkvTh, KDIM, QKVCOLS);
    transpose32h<<<dim3(CDIM / 32, KDIM / 32), dim3(32, 8)>>>(Wproj, wprojTh, KDIM, CDIM);

    // QKV projection -> fp16 (Q columns pre-scaled by 0.125*log2e)
    cudaFuncSetAttribute(gemm_mma_h<false, true>,
                         cudaFuncAttributeMaxDynamicSharedMemorySize, GS_TOTAL);
    cudaFuncSetAttribute(gemm_mma_h<true, false>,
                         cudaFuncAttributeMaxDynamicSharedMemorySize, GS_TOTAL);
    gemm_mma_h<false, true><<<dim3(QKVCOLS / 128, MROWS / 128), 128, GS_TOTAL>>>(
        xh, wqkvTh, nullptr, qkvh, QKVCOLS);

    // V^T per head
    vtrans_h<<<dim3(NDIM / 32, DHEAD / 32, BDIM * HDIM), dim3(32, 8)>>>(qkvh, vTh);

    // Attention
    cudaFuncSetAttribute(attn_mma_h,
                         cudaFuncAttributeMaxDynamicSharedMemorySize, AS_TOTAL);
    attn_mma_h<<<dim3(NDIM / 128, BDIM * HDIM), 128, AS_TOTAL>>>(
        qkvh, vTh, attnP, padP, ctxh);

    // Output projection + bias -> fp32
    gemm_mma_h<true, false><<<dim3(CDIM / 128, MROWS / 128), 128, GS_TOTAL>>>(
        ctxh, wprojTh, bias, out, CDIM);
}